// round 1
// baseline (speedup 1.0000x reference)
#include <cuda_runtime.h>
#include <math.h>

#define Bb 4
#define Tt 4096
#define Ee 1024
#define Hh 16
#define Dd 64
#define M_ROWS (Bb*Tt)          // 16384
#define FF (4*Ee)               // 4096
#define PIO2 1.5707963267948966f

// ---------------- scratch (device globals; allocation-free) ----------------
__device__ float g_h   [M_ROWS*Ee];   // LN1 out, later LN2 out
__device__ float g_q   [M_ROWS*Ee];
__device__ float g_k   [M_ROWS*Ee];
__device__ float g_v   [M_ROWS*Ee];
__device__ float g_attn[M_ROWS*Ee];   // attention output (pre-Wo)
__device__ float g_x2  [M_ROWS*Ee];   // x + attn
__device__ float g_fc  [M_ROWS*FF];   // gelu(fc)
__device__ float g_kv  [Bb*Hh*128*Dd];
__device__ float g_ksum[Bb*Hh*128];

// ---------------- LayerNorm: one block per row of 1024 ----------------
__global__ void ln_kernel(const float* __restrict__ X, const float* __restrict__ w,
                          const float* __restrict__ b, float* __restrict__ Y) {
    int row = blockIdx.x;
    int tid = threadIdx.x;                 // 256 threads
    const float4* x4 = (const float4*)(X + (size_t)row * Ee);
    float4 v = x4[tid];
    __shared__ float red[8];

    float s = v.x + v.y + v.z + v.w;
    for (int o = 16; o > 0; o >>= 1) s += __shfl_down_sync(0xffffffffu, s, o);
    if ((tid & 31) == 0) red[tid >> 5] = s;
    __syncthreads();
    if (tid < 8) {
        float t = red[tid];
        for (int o = 4; o > 0; o >>= 1) t += __shfl_down_sync(0xffu, t, o);
        if (tid == 0) red[0] = t;
    }
    __syncthreads();
    float mu = red[0] * (1.0f / Ee);
    __syncthreads();

    float dx = v.x - mu, dy = v.y - mu, dz = v.z - mu, dw = v.w - mu;
    float ss = dx*dx + dy*dy + dz*dz + dw*dw;
    for (int o = 16; o > 0; o >>= 1) ss += __shfl_down_sync(0xffffffffu, ss, o);
    if ((tid & 31) == 0) red[tid >> 5] = ss;
    __syncthreads();
    if (tid < 8) {
        float t = red[tid];
        for (int o = 4; o > 0; o >>= 1) t += __shfl_down_sync(0xffu, t, o);
        if (tid == 0) red[0] = t;
    }
    __syncthreads();
    float rstd = rsqrtf(red[0] * (1.0f / Ee) + 1e-5f);

    float4 wv = ((const float4*)w)[tid];
    float4 bv = ((const float4*)b)[tid];
    float4 o;
    o.x = dx * rstd * wv.x + bv.x;
    o.y = dy * rstd * wv.y + bv.y;
    o.z = dz * rstd * wv.z + bv.z;
    o.w = dw * rstd * wv.w + bv.w;
    ((float4*)(Y + (size_t)row * Ee))[tid] = o;
}

// ---------------- fp32 SGEMM 128x128 tile, 8x8/thread, fused epilogue ------
// C[m,n] = act( A[m,:]@B[:,n] + bias[n] ) (+ res[m,n])
// ACT: 0=none, 1=relu, 2=gelu(exact)
template<int ACT, bool RES>
__global__ __launch_bounds__(256) void gemm128(
    const float* __restrict__ A, const float* __restrict__ B,
    const float* __restrict__ bias, const float* __restrict__ res,
    float* __restrict__ C, int M, int N, int K)
{
    __shared__ float As[16][128];
    __shared__ float Bs[16][128];
    int tid = threadIdx.x;
    int bx = blockIdx.x, by = blockIdx.y;
    int tx = tid & 15, ty = tid >> 4;

    float acc[8][8];
#pragma unroll
    for (int i = 0; i < 8; i++)
#pragma unroll
        for (int j = 0; j < 8; j++) acc[i][j] = 0.0f;

    for (int k0 = 0; k0 < K; k0 += 16) {
        // load A tile 128x16 (transposed into As[k][m])
#pragma unroll
        for (int ld = 0; ld < 2; ld++) {
            int id = tid + ld * 256;             // 0..511 float4
            int r = id >> 2, c4 = (id & 3) * 4;
            float4 a = *(const float4*)&A[(size_t)(by * 128 + r) * K + k0 + c4];
            As[c4 + 0][r] = a.x;
            As[c4 + 1][r] = a.y;
            As[c4 + 2][r] = a.z;
            As[c4 + 3][r] = a.w;
        }
        // load B tile 16x128
#pragma unroll
        for (int ld = 0; ld < 2; ld++) {
            int id = tid + ld * 256;
            int r = id >> 5, c4 = (id & 31) * 4;
            *(float4*)&Bs[r][c4] =
                *(const float4*)&B[(size_t)(k0 + r) * N + bx * 128 + c4];
        }
        __syncthreads();
#pragma unroll
        for (int kk = 0; kk < 16; kk++) {
            float4 a0 = *(const float4*)&As[kk][ty * 8];
            float4 a1 = *(const float4*)&As[kk][ty * 8 + 4];
            float4 b0 = *(const float4*)&Bs[kk][tx * 8];
            float4 b1 = *(const float4*)&Bs[kk][tx * 8 + 4];
            float ar[8] = {a0.x,a0.y,a0.z,a0.w,a1.x,a1.y,a1.z,a1.w};
            float br[8] = {b0.x,b0.y,b0.z,b0.w,b1.x,b1.y,b1.z,b1.w};
#pragma unroll
            for (int i = 0; i < 8; i++)
#pragma unroll
                for (int j = 0; j < 8; j++)
                    acc[i][j] = fmaf(ar[i], br[j], acc[i][j]);
        }
        __syncthreads();
    }

    int m0 = by * 128 + ty * 8;
    int n0 = bx * 128 + tx * 8;
    float4 bs0 = *(const float4*)&bias[n0];
    float4 bs1 = *(const float4*)&bias[n0 + 4];
    float bb[8] = {bs0.x,bs0.y,bs0.z,bs0.w,bs1.x,bs1.y,bs1.z,bs1.w};
#pragma unroll
    for (int i = 0; i < 8; i++) {
        float c[8];
#pragma unroll
        for (int j = 0; j < 8; j++) {
            float v = acc[i][j] + bb[j];
            if (ACT == 1) v = fmaxf(v, 0.0f);
            else if (ACT == 2) v = 0.5f * v * (1.0f + erff(v * 0.70710678118654752f));
            c[j] = v;
        }
        size_t off = (size_t)(m0 + i) * N + n0;
        if (RES) {
            float4 r0 = *(const float4*)&res[off];
            float4 r1 = *(const float4*)&res[off + 4];
            c[0]+=r0.x; c[1]+=r0.y; c[2]+=r0.z; c[3]+=r0.w;
            c[4]+=r1.x; c[5]+=r1.y; c[6]+=r1.z; c[7]+=r1.w;
        }
        *(float4*)&C[off]     = make_float4(c[0],c[1],c[2],c[3]);
        *(float4*)&C[off + 4] = make_float4(c[4],c[5],c[6],c[7]);
    }
}

// ---------------- zero small accumulators ----------------
__global__ void zero_kernel(float* p, int n) {
    int i = blockIdx.x * blockDim.x + threadIdx.x;
    if (i < n) p[i] = 0.0f;
}

// ---------------- kv = sum_t k_[t,:]^T v[t,:], ksum = sum_t k_[t,:] --------
// grid (B*H, TSPLIT), block 256
#define TSPLIT 4
__global__ __launch_bounds__(256) void kv_kernel(
    const float* __restrict__ Kp, const float* __restrict__ Vp,
    float* __restrict__ kv, float* __restrict__ ksum)
{
    int bh = blockIdx.x;
    int b = bh >> 4, h = bh & 15;
    int tid = threadIdx.x;
    __shared__ float ks_sh[32][64];
    __shared__ float vs_sh[32][64];
    __shared__ float s_sh[32], c_sh[32];

    int dd = tid & 63;
    int eb = tid >> 6;          // 0..3
    int e0 = eb * 16;
    float acc_s[16], acc_c[16];
#pragma unroll
    for (int i = 0; i < 16; i++) { acc_s[i] = 0.0f; acc_c[i] = 0.0f; }
    float ksum_s = 0.0f, ksum_c = 0.0f;

    int tbase = blockIdx.y * (Tt / TSPLIT);
    for (int tt = 0; tt < Tt / TSPLIT; tt += 32) {
        int t0 = tbase + tt;
#pragma unroll
        for (int ld = 0; ld < 2; ld++) {
            int id = tid + ld * 256;        // 512 float4 slots per tensor
            int r = id >> 4, c4 = (id & 15) * 4;
            size_t off = (size_t)(b * Tt + t0 + r) * Ee + h * 64 + c4;
            *(float4*)&ks_sh[r][c4] = *(const float4*)&Kp[off];
            *(float4*)&vs_sh[r][c4] = *(const float4*)&Vp[off];
        }
        if (tid < 32) {
            float idx = PIO2 * (float)(t0 + tid + 1) * (1.0f / Tt);
            s_sh[tid] = sinf(idx);
            c_sh[tid] = cosf(idx);
        }
        __syncthreads();
#pragma unroll 4
        for (int r = 0; r < 32; r++) {
            float kd = ks_sh[r][dd];
            float as = kd * s_sh[r];
            float ac = kd * c_sh[r];
            if (eb == 0) { ksum_s += as; ksum_c += ac; }
#pragma unroll
            for (int i = 0; i < 16; i++) {
                float ve = vs_sh[r][e0 + i];
                acc_s[i] = fmaf(as, ve, acc_s[i]);
                acc_c[i] = fmaf(ac, ve, acc_c[i]);
            }
        }
        __syncthreads();
    }
    float* kvb = kv + (size_t)bh * 128 * Dd;
#pragma unroll
    for (int i = 0; i < 16; i++) {
        atomicAdd(&kvb[dd * Dd + e0 + i], acc_s[i]);
        atomicAdd(&kvb[(64 + dd) * Dd + e0 + i], acc_c[i]);
    }
    if (eb == 0) {
        atomicAdd(&ksum[bh * 128 + dd], ksum_s);
        atomicAdd(&ksum[bh * 128 + 64 + dd], ksum_c);
    }
}

// ---------------- out = z * q_ @ kv  (per head, 32 t per block) -----------
// grid (T/32, B*H), block 256
__global__ __launch_bounds__(256) void attn_kernel(
    const float* __restrict__ Qp, const float* __restrict__ kv,
    const float* __restrict__ ksum, float* __restrict__ outp)
{
    int bh = blockIdx.y;
    int b = bh >> 4, h = bh & 15;
    int t0 = blockIdx.x * 32;
    int tid = threadIdx.x;

    __shared__ float kv_sh[128][64];      // 32KB
    __shared__ float q_sh[32][65];        // padded, conflict-free column reads
    __shared__ float ksum_sh[128];
    __shared__ float den_sh[32], s_sh[32], c_sh[32];

#pragma unroll
    for (int ld = 0; ld < 8; ld++) {
        int id = tid + ld * 256;          // 2048 float4
        int r = id >> 4, c4 = (id & 15) * 4;
        *(float4*)&kv_sh[r][c4] = *(const float4*)&kv[((size_t)bh * 128 + r) * Dd + c4];
    }
#pragma unroll
    for (int ld = 0; ld < 2; ld++) {
        int id = tid + ld * 256;          // 512 float4
        int r = id >> 4, c4 = (id & 15) * 4;
        float4 qv = *(const float4*)&Qp[(size_t)(b * Tt + t0 + r) * Ee + h * 64 + c4];
        q_sh[r][c4 + 0] = qv.x; q_sh[r][c4 + 1] = qv.y;
        q_sh[r][c4 + 2] = qv.z; q_sh[r][c4 + 3] = qv.w;
    }
    if (tid < 128) ksum_sh[tid] = ksum[bh * 128 + tid];
    if (tid < 32) {
        float idx = PIO2 * (float)(t0 + tid + 1) * (1.0f / Tt);
        s_sh[tid] = sinf(idx);
        c_sh[tid] = cosf(idx);
    }
    __syncthreads();

    if (tid < 32) {
        float ds = 0.0f, dc = 0.0f;
#pragma unroll 8
        for (int d = 0; d < 64; d++) {
            float qd = q_sh[tid][d];
            ds = fmaf(qd, ksum_sh[d], ds);
            dc = fmaf(qd, ksum_sh[64 + d], dc);
        }
        den_sh[tid] = s_sh[tid] * ds + c_sh[tid] * dc;
    }
    __syncthreads();

    int tl = tid & 31;
    int eb = tid >> 5;                    // warp-uniform -> kv reads broadcast
    int e0 = eb * 8;
    float outs[8], outc[8];
#pragma unroll
    for (int j = 0; j < 8; j++) { outs[j] = 0.0f; outc[j] = 0.0f; }

#pragma unroll 4
    for (int d = 0; d < 64; d++) {
        float qd = q_sh[tl][d];
        float4 k0 = *(const float4*)&kv_sh[d][e0];
        float4 k1 = *(const float4*)&kv_sh[d][e0 + 4];
        float4 m0 = *(const float4*)&kv_sh[64 + d][e0];
        float4 m1 = *(const float4*)&kv_sh[64 + d][e0 + 4];
        outs[0]=fmaf(qd,k0.x,outs[0]); outs[1]=fmaf(qd,k0.y,outs[1]);
        outs[2]=fmaf(qd,k0.z,outs[2]); outs[3]=fmaf(qd,k0.w,outs[3]);
        outs[4]=fmaf(qd,k1.x,outs[4]); outs[5]=fmaf(qd,k1.y,outs[5]);
        outs[6]=fmaf(qd,k1.z,outs[6]); outs[7]=fmaf(qd,k1.w,outs[7]);
        outc[0]=fmaf(qd,m0.x,outc[0]); outc[1]=fmaf(qd,m0.y,outc[1]);
        outc[2]=fmaf(qd,m0.z,outc[2]); outc[3]=fmaf(qd,m0.w,outc[3]);
        outc[4]=fmaf(qd,m1.x,outc[4]); outc[5]=fmaf(qd,m1.y,outc[5]);
        outc[6]=fmaf(qd,m1.z,outc[6]); outc[7]=fmaf(qd,m1.w,outc[7]);
    }
    float z = 1.0f / fmaxf(den_sh[tl], 1e-6f);
    float s = s_sh[tl] * z, c = c_sh[tl] * z;
    float o[8];
#pragma unroll
    for (int j = 0; j < 8; j++) o[j] = s * outs[j] + c * outc[j];
    size_t off = (size_t)(b * Tt + t0 + tl) * Ee + h * 64 + e0;
    *(float4*)&outp[off]     = make_float4(o[0],o[1],o[2],o[3]);
    *(float4*)&outp[off + 4] = make_float4(o[4],o[5],o[6],o[7]);
}

// ---------------- launch ----------------
extern "C" void kernel_launch(void* const* d_in, const int* in_sizes, int n_in,
                              void* d_out, int out_size) {
    const float* x      = (const float*)d_in[0];
    const float* ln1_w  = (const float*)d_in[1];
    const float* ln1_b  = (const float*)d_in[2];
    const float* wq     = (const float*)d_in[3];
    const float* bq     = (const float*)d_in[4];
    const float* wk     = (const float*)d_in[5];
    const float* bk     = (const float*)d_in[6];
    const float* wv     = (const float*)d_in[7];
    const float* bv     = (const float*)d_in[8];
    const float* wo     = (const float*)d_in[9];
    const float* bo     = (const float*)d_in[10];
    const float* ln2_w  = (const float*)d_in[11];
    const float* ln2_b  = (const float*)d_in[12];
    const float* w_fc   = (const float*)d_in[13];
    const float* b_fc   = (const float*)d_in[14];
    const float* w_proj = (const float*)d_in[15];
    const float* b_proj = (const float*)d_in[16];
    float* out = (float*)d_out;

    float *p_h, *p_q, *p_k, *p_v, *p_attn, *p_x2, *p_fc, *p_kv, *p_ksum;
    cudaGetSymbolAddress((void**)&p_h,    g_h);
    cudaGetSymbolAddress((void**)&p_q,    g_q);
    cudaGetSymbolAddress((void**)&p_k,    g_k);
    cudaGetSymbolAddress((void**)&p_v,    g_v);
    cudaGetSymbolAddress((void**)&p_attn, g_attn);
    cudaGetSymbolAddress((void**)&p_x2,   g_x2);
    cudaGetSymbolAddress((void**)&p_fc,   g_fc);
    cudaGetSymbolAddress((void**)&p_kv,   g_kv);
    cudaGetSymbolAddress((void**)&p_ksum, g_ksum);

    // 1. h = LN1(x)
    ln_kernel<<<M_ROWS, 256>>>(x, ln1_w, ln1_b, p_h);

    // 2-4. q,k,v projections
    dim3 g1(Ee / 128, M_ROWS / 128);
    gemm128<1, false><<<g1, 256>>>(p_h, wq, bq, nullptr, p_q, M_ROWS, Ee, Ee);
    gemm128<1, false><<<g1, 256>>>(p_h, wk, bk, nullptr, p_k, M_ROWS, Ee, Ee);
    gemm128<0, false><<<g1, 256>>>(p_h, wv, bv, nullptr, p_v, M_ROWS, Ee, Ee);

    // 5-6. kv / ksum reduction
    int nz = Bb * Hh * 128 * Dd + Bb * Hh * 128;
    zero_kernel<<<(nz + 255) / 256, 256>>>(p_kv, nz);  // g_ksum follows g_kv? no — zero both explicitly
    zero_kernel<<<(Bb * Hh * 128 + 255) / 256, 256>>>(p_ksum, Bb * Hh * 128);
    kv_kernel<<<dim3(Bb * Hh, TSPLIT), 256>>>(p_k, p_v, p_kv, p_ksum);

    // 7. attention output
    attn_kernel<<<dim3(Tt / 32, Bb * Hh), 256>>>(p_q, p_kv, p_ksum, p_attn);

    // 8. x2 = x + attn @ wo + bo
    gemm128<0, true><<<g1, 256>>>(p_attn, wo, bo, x, p_x2, M_ROWS, Ee, Ee);

    // 9. h = LN2(x2)
    ln_kernel<<<M_ROWS, 256>>>(p_x2, ln2_w, ln2_b, p_h);

    // 10. fc = gelu(h @ w_fc + b_fc)
    dim3 g2(FF / 128, M_ROWS / 128);
    gemm128<2, false><<<g2, 256>>>(p_h, w_fc, b_fc, nullptr, p_fc, M_ROWS, FF, Ee);

    // 11. out = x2 + fc @ w_proj + b_proj
    gemm128<0, true><<<g1, 256>>>(p_fc, w_proj, b_proj, p_x2, out, M_ROWS, Ee, FF);
}

// round 3
// speedup vs baseline: 1.9735x; 1.9735x over previous
#include <cuda_runtime.h>
#include <cuda_bf16.h>
#include <math.h>
#include <stdint.h>

#define Bb 4
#define Tt 4096
#define Ee 1024
#define Hh 16
#define Dd 64
#define M_ROWS (Bb*Tt)          // 16384
#define FF (4*Ee)               // 4096
#define PIO2 1.5707963267948966f

// ===================== PTX helpers (baseline ISA only — no 'a' features) ===
__device__ __forceinline__ uint32_t smem_to_u32(const void* p) {
    uint32_t a;
    asm("{ .reg .u64 t; cvta.to.shared.u64 t, %1; cvt.u32.u64 %0, t; }" : "=r"(a) : "l"(p));
    return a;
}
#define CP_ASYNC16(saddr, gptr) \
    asm volatile("cp.async.cg.shared.global [%0], [%1], 16;" :: "r"(saddr), "l"(gptr))
#define CP_COMMIT() asm volatile("cp.async.commit_group;" ::: "memory")
#define CP_WAIT1()  asm volatile("cp.async.wait_group 1;" ::: "memory")

#define LDSM_X4(r0,r1,r2,r3, addr) \
    asm volatile("ldmatrix.sync.aligned.m8n8.x4.shared.b16 {%0,%1,%2,%3}, [%4];" \
        : "=r"(r0),"=r"(r1),"=r"(r2),"=r"(r3) : "r"(addr))

#define MMA_BF16(d, a, b) \
    asm volatile("mma.sync.aligned.m16n8k16.row.col.f32.bf16.bf16.f32 " \
        "{%0,%1,%2,%3}, {%4,%5,%6,%7}, {%8,%9}, {%0,%1,%2,%3};" \
        : "+f"((d)[0]),"+f"((d)[1]),"+f"((d)[2]),"+f"((d)[3]) \
        : "r"((a)[0]),"r"((a)[1]),"r"((a)[2]),"r"((a)[3]), "r"((b)[0]),"r"((b)[1]))

__device__ __forceinline__ void split2(float a, float b, uint32_t& hp, uint32_t& lp) {
    __nv_bfloat16 ha = __float2bfloat16(a), hb = __float2bfloat16(b);
    __nv_bfloat16 la = __float2bfloat16(a - __bfloat162float(ha));
    __nv_bfloat16 lb = __float2bfloat16(b - __bfloat162float(hb));
    hp = (uint32_t)__bfloat16_as_ushort(ha) | ((uint32_t)__bfloat16_as_ushort(hb) << 16);
    lp = (uint32_t)__bfloat16_as_ushort(la) | ((uint32_t)__bfloat16_as_ushort(lb) << 16);
}

// ===================== scratch (device globals) =====================
__device__ __nv_bfloat16 g_h_hi   [M_ROWS*Ee];
__device__ __nv_bfloat16 g_h_lo   [M_ROWS*Ee];
__device__ __nv_bfloat16 g_attn_hi[M_ROWS*Ee];
__device__ __nv_bfloat16 g_attn_lo[M_ROWS*Ee];
__device__ __nv_bfloat16 g_fc_hi  [(size_t)M_ROWS*FF];
__device__ __nv_bfloat16 g_fc_lo  [(size_t)M_ROWS*FF];
__device__ float g_q [M_ROWS*Ee];
__device__ float g_k [M_ROWS*Ee];
__device__ float g_v [M_ROWS*Ee];
__device__ float g_x2[M_ROWS*Ee];
__device__ float g_kv  [Bb*Hh*128*Dd];
__device__ float g_ksum[Bb*Hh*128];
// transposed split weights: [N, K] bf16
__device__ __nv_bfloat16 g_wq_hi[Ee*Ee],  g_wq_lo[Ee*Ee];
__device__ __nv_bfloat16 g_wk_hi[Ee*Ee],  g_wk_lo[Ee*Ee];
__device__ __nv_bfloat16 g_wv_hi[Ee*Ee],  g_wv_lo[Ee*Ee];
__device__ __nv_bfloat16 g_wo_hi[Ee*Ee],  g_wo_lo[Ee*Ee];
__device__ __nv_bfloat16 g_wfc_hi[(size_t)FF*Ee], g_wfc_lo[(size_t)FF*Ee];
__device__ __nv_bfloat16 g_wpj_hi[(size_t)Ee*FF], g_wpj_lo[(size_t)Ee*FF];

// ===================== transpose + split: W[K,N] -> T_hi/lo[N,K] ===========
__global__ void transpose_split_kernel(const float* __restrict__ W,
                                       __nv_bfloat16* __restrict__ Th,
                                       __nv_bfloat16* __restrict__ Tl, int K, int N) {
    __shared__ float ts[32][33];
    int n0 = blockIdx.x * 32, k0 = blockIdx.y * 32;
    int tx = threadIdx.x & 31, ty = threadIdx.x >> 5;
#pragma unroll
    for (int i = 0; i < 32; i += 8)
        ts[ty + i][tx] = W[(size_t)(k0 + ty + i) * N + n0 + tx];
    __syncthreads();
#pragma unroll
    for (int i = 0; i < 32; i += 8) {
        float v = ts[tx][ty + i];
        __nv_bfloat16 h = __float2bfloat16(v);
        __nv_bfloat16 l = __float2bfloat16(v - __bfloat162float(h));
        size_t off = (size_t)(n0 + ty + i) * K + k0 + tx;
        Th[off] = h;
        Tl[off] = l;
    }
}

// ===================== LayerNorm -> bf16 hi/lo =====================
__global__ void ln_kernel(const float* __restrict__ X, const float* __restrict__ w,
                          const float* __restrict__ b,
                          __nv_bfloat16* __restrict__ Yhi, __nv_bfloat16* __restrict__ Ylo) {
    int row = blockIdx.x;
    int tid = threadIdx.x;                 // 256 threads
    const float4* x4 = (const float4*)(X + (size_t)row * Ee);
    float4 v = x4[tid];
    __shared__ float red[8];

    float s = v.x + v.y + v.z + v.w;
    for (int o = 16; o > 0; o >>= 1) s += __shfl_down_sync(0xffffffffu, s, o);
    if ((tid & 31) == 0) red[tid >> 5] = s;
    __syncthreads();
    if (tid < 8) {
        float t = red[tid];
        for (int o = 4; o > 0; o >>= 1) t += __shfl_down_sync(0xffu, t, o);
        if (tid == 0) red[0] = t;
    }
    __syncthreads();
    float mu = red[0] * (1.0f / Ee);
    __syncthreads();

    float dx = v.x - mu, dy = v.y - mu, dz = v.z - mu, dw = v.w - mu;
    float ss = dx*dx + dy*dy + dz*dz + dw*dw;
    for (int o = 16; o > 0; o >>= 1) ss += __shfl_down_sync(0xffffffffu, ss, o);
    if ((tid & 31) == 0) red[tid >> 5] = ss;
    __syncthreads();
    if (tid < 8) {
        float t = red[tid];
        for (int o = 4; o > 0; o >>= 1) t += __shfl_down_sync(0xffu, t, o);
        if (tid == 0) red[0] = t;
    }
    __syncthreads();
    float rstd = rsqrtf(red[0] * (1.0f / Ee) + 1e-5f);

    float4 wv = ((const float4*)w)[tid];
    float4 bv = ((const float4*)b)[tid];
    float ox = dx * rstd * wv.x + bv.x;
    float oy = dy * rstd * wv.y + bv.y;
    float oz = dz * rstd * wv.z + bv.z;
    float ow = dw * rstd * wv.w + bv.w;
    uint32_t h0, l0, h1, l1;
    split2(ox, oy, h0, l0);
    split2(oz, ow, h1, l1);
    size_t off = (size_t)row * Ee + tid * 4;
    *(uint2*)&Yhi[off] = make_uint2(h0, h1);
    *(uint2*)&Ylo[off] = make_uint2(l0, l1);
}

// ===================== mma.sync split-bf16 GEMM ============================
// C[m,n] = act( A[m,:] @ Bt[n,:]^T + bias[n] ) (+ res)
// A: [M,K] bf16 hi/lo, Bt: [N,K] bf16 hi/lo. Tile 128x128, K-chunk 64.
// 2-stage cp.async pipeline. ACT: 0 none, 1 relu, 2 gelu. OSPLIT: fp32 / bf16 pair.
#define STAGE_BYTES 65536
#define GT_SMEM (2*STAGE_BYTES)

__device__ __forceinline__ void load_stage(
    uint32_t sbase, int stage, int tid, int m0, int n0, int k0, int K,
    const __nv_bfloat16* Ahi, const __nv_bfloat16* Alo,
    const __nv_bfloat16* Bhi, const __nv_bfloat16* Blo)
{
    uint32_t sb = sbase + stage * STAGE_BYTES;
#pragma unroll
    for (int i = 0; i < 4; i++) {
        int u = tid + i * 256;        // 0..1023
        int r = u >> 3, s = u & 7;
        uint32_t soff = (uint32_t)(r * 128) + (uint32_t)(((s ^ (r & 7)) << 4));
        size_t gA = (size_t)(m0 + r) * K + k0 + s * 8;
        size_t gB = (size_t)(n0 + r) * K + k0 + s * 8;
        CP_ASYNC16(sb + soff,         Ahi + gA);
        CP_ASYNC16(sb + 16384 + soff, Alo + gA);
        CP_ASYNC16(sb + 32768 + soff, Bhi + gB);
        CP_ASYNC16(sb + 49152 + soff, Blo + gB);
    }
}

template<int ACT, bool RES, int OSPLIT>
__global__ __launch_bounds__(256, 1) void gemm_mma(
    const __nv_bfloat16* __restrict__ Ahi, const __nv_bfloat16* __restrict__ Alo,
    const __nv_bfloat16* __restrict__ Bhi, const __nv_bfloat16* __restrict__ Blo,
    const float* __restrict__ bias, const float* __restrict__ res,
    float* __restrict__ Cf, __nv_bfloat16* __restrict__ Chi, __nv_bfloat16* __restrict__ Clo,
    int M, int N, int K)
{
    extern __shared__ char smem[];
    uint32_t sbase = smem_to_u32(smem);
    int tid = threadIdx.x;
    int wid = tid >> 5, l = tid & 31;
    int warpM = wid >> 2, warpN = wid & 3;     // 2 x 4 warps, warp tile 64x32
    int m0 = blockIdx.y * 128, n0 = blockIdx.x * 128;

    int g = l & 7, grp = l >> 3;
    // ldmatrix per-lane base offsets (swizzle xor value is g for all)
    uint32_t constA = (uint32_t)((warpM * 64 + (grp & 1) * 8 + g) * 128);
    int khA = grp >> 1;
    uint32_t constB = (uint32_t)((warpN * 32 + (grp >> 1) * 8 + g) * 128);
    int khB = grp & 1;

    float acc[4][4][4];
#pragma unroll
    for (int mi = 0; mi < 4; mi++)
#pragma unroll
        for (int ni = 0; ni < 4; ni++)
#pragma unroll
            for (int j = 0; j < 4; j++) acc[mi][ni][j] = 0.0f;

    const int NC = K >> 6;
    load_stage(sbase, 0, tid, m0, n0, 0, K, Ahi, Alo, Bhi, Blo);
    CP_COMMIT();
    load_stage(sbase, 1, tid, m0, n0, 64, K, Ahi, Alo, Bhi, Blo);
    CP_COMMIT();

    for (int c = 0; c < NC; c++) {
        CP_WAIT1();
        __syncthreads();
        int stage = c & 1;
        uint32_t sA = sbase + stage * STAGE_BYTES;
        uint32_t sB = sA + 32768;
#pragma unroll
        for (int ks = 0; ks < 4; ks++) {
            uint32_t Ah[4][4], Al4[4][4], Bh[4][2], Bl[4][2];
            uint32_t segA = (uint32_t)(((ks * 2 + khA) ^ g) << 4);
            uint32_t segB = (uint32_t)(((ks * 2 + khB) ^ g) << 4);
#pragma unroll
            for (int mi = 0; mi < 4; mi++) {
                uint32_t ad = sA + constA + mi * 2048 + segA;
                LDSM_X4(Ah[mi][0], Ah[mi][1], Ah[mi][2], Ah[mi][3], ad);
                LDSM_X4(Al4[mi][0], Al4[mi][1], Al4[mi][2], Al4[mi][3], ad + 16384);
            }
#pragma unroll
            for (int np = 0; np < 2; np++) {
                uint32_t bd = sB + constB + np * 2048 + segB;
                uint32_t t0, t1, t2, t3;
                LDSM_X4(t0, t1, t2, t3, bd);
                Bh[np*2][0] = t0; Bh[np*2][1] = t1; Bh[np*2+1][0] = t2; Bh[np*2+1][1] = t3;
                LDSM_X4(t0, t1, t2, t3, bd + 16384);
                Bl[np*2][0] = t0; Bl[np*2][1] = t1; Bl[np*2+1][0] = t2; Bl[np*2+1][1] = t3;
            }
#pragma unroll
            for (int mi = 0; mi < 4; mi++) {
#pragma unroll
                for (int ni = 0; ni < 4; ni++) {
                    MMA_BF16(acc[mi][ni], Ah[mi], Bh[ni]);
                    MMA_BF16(acc[mi][ni], Ah[mi], Bl[ni]);
                    MMA_BF16(acc[mi][ni], Al4[mi], Bh[ni]);
                }
            }
        }
        __syncthreads();
        if (c + 2 < NC)
            load_stage(sbase, stage, tid, m0, n0, (c + 2) * 64, K, Ahi, Alo, Bhi, Blo);
        CP_COMMIT();
    }

    // ---------------- epilogue ----------------
#pragma unroll
    for (int mi = 0; mi < 4; mi++) {
#pragma unroll
        for (int half = 0; half < 2; half++) {
            int m = m0 + warpM * 64 + mi * 16 + (l >> 2) + half * 8;
#pragma unroll
            for (int ni = 0; ni < 4; ni++) {
                int n = n0 + warpN * 32 + ni * 8 + (l & 3) * 2;
                float v0 = acc[mi][ni][half * 2 + 0];
                float v1 = acc[mi][ni][half * 2 + 1];
                float2 bz = __ldg((const float2*)&bias[n]);
                v0 += bz.x; v1 += bz.y;
                if (ACT == 1) { v0 = fmaxf(v0, 0.0f); v1 = fmaxf(v1, 0.0f); }
                else if (ACT == 2) {
                    v0 = 0.5f * v0 * (1.0f + erff(v0 * 0.70710678118654752f));
                    v1 = 0.5f * v1 * (1.0f + erff(v1 * 0.70710678118654752f));
                }
                size_t off = (size_t)m * N + n;
                if (RES) {
                    float2 rv = *(const float2*)&res[off];
                    v0 += rv.x; v1 += rv.y;
                }
                if (OSPLIT == 0) {
                    *(float2*)&Cf[off] = make_float2(v0, v1);
                } else {
                    uint32_t hp, lp;
                    split2(v0, v1, hp, lp);
                    *(uint32_t*)&Chi[off] = hp;
                    *(uint32_t*)&Clo[off] = lp;
                }
            }
        }
    }
}

// ===================== zero =====================
__global__ void zero_kernel(float* p, int n) {
    int i = blockIdx.x * blockDim.x + threadIdx.x;
    if (i < n) p[i] = 0.0f;
}

// ===================== kv reduction =====================
#define TSPLIT 4
__global__ __launch_bounds__(256) void kv_kernel(
    const float* __restrict__ Kp, const float* __restrict__ Vp,
    float* __restrict__ kv, float* __restrict__ ksum)
{
    int bh = blockIdx.x;
    int b = bh >> 4, h = bh & 15;
    int tid = threadIdx.x;
    __shared__ float ks_sh[32][64];
    __shared__ float vs_sh[32][64];
    __shared__ float s_sh[32], c_sh[32];

    int dd = tid & 63;
    int eb = tid >> 6;
    int e0 = eb * 16;
    float acc_s[16], acc_c[16];
#pragma unroll
    for (int i = 0; i < 16; i++) { acc_s[i] = 0.0f; acc_c[i] = 0.0f; }
    float ksum_s = 0.0f, ksum_c = 0.0f;

    int tbase = blockIdx.y * (Tt / TSPLIT);
    for (int tt = 0; tt < Tt / TSPLIT; tt += 32) {
        int t0 = tbase + tt;
#pragma unroll
        for (int ld = 0; ld < 2; ld++) {
            int id = tid + ld * 256;
            int r = id >> 4, c4 = (id & 15) * 4;
            size_t off = (size_t)(b * Tt + t0 + r) * Ee + h * 64 + c4;
            *(float4*)&ks_sh[r][c4] = *(const float4*)&Kp[off];
            *(float4*)&vs_sh[r][c4] = *(const float4*)&Vp[off];
        }
        if (tid < 32) {
            float idx = PIO2 * (float)(t0 + tid + 1) * (1.0f / Tt);
            s_sh[tid] = sinf(idx);
            c_sh[tid] = cosf(idx);
        }
        __syncthreads();
#pragma unroll 4
        for (int r = 0; r < 32; r++) {
            float kd = ks_sh[r][dd];
            float as = kd * s_sh[r];
            float ac = kd * c_sh[r];
            if (eb == 0) { ksum_s += as; ksum_c += ac; }
#pragma unroll
            for (int i = 0; i < 16; i++) {
                float ve = vs_sh[r][e0 + i];
                acc_s[i] = fmaf(as, ve, acc_s[i]);
                acc_c[i] = fmaf(ac, ve, acc_c[i]);
            }
        }
        __syncthreads();
    }
    float* kvb = kv + (size_t)bh * 128 * Dd;
#pragma unroll
    for (int i = 0; i < 16; i++) {
        atomicAdd(&kvb[dd * Dd + e0 + i], acc_s[i]);
        atomicAdd(&kvb[(64 + dd) * Dd + e0 + i], acc_c[i]);
    }
    if (eb == 0) {
        atomicAdd(&ksum[bh * 128 + dd], ksum_s);
        atomicAdd(&ksum[bh * 128 + 64 + dd], ksum_c);
    }
}

// ===================== attention: out -> bf16 hi/lo =====================
__global__ __launch_bounds__(256) void attn_kernel(
    const float* __restrict__ Qp, const float* __restrict__ kv,
    const float* __restrict__ ksum,
    __nv_bfloat16* __restrict__ Ohi, __nv_bfloat16* __restrict__ Olo)
{
    int bh = blockIdx.y;
    int b = bh >> 4, h = bh & 15;
    int t0 = blockIdx.x * 32;
    int tid = threadIdx.x;

    __shared__ float kv_sh[128][64];
    __shared__ float q_sh[32][65];
    __shared__ float ksum_sh[128];
    __shared__ float den_sh[32], s_sh[32], c_sh[32];

#pragma unroll
    for (int ld = 0; ld < 8; ld++) {
        int id = tid + ld * 256;
        int r = id >> 4, c4 = (id & 15) * 4;
        *(float4*)&kv_sh[r][c4] = *(const float4*)&kv[((size_t)bh * 128 + r) * Dd + c4];
    }
#pragma unroll
    for (int ld = 0; ld < 2; ld++) {
        int id = tid + ld * 256;
        int r = id >> 4, c4 = (id & 15) * 4;
        float4 qv = *(const float4*)&Qp[(size_t)(b * Tt + t0 + r) * Ee + h * 64 + c4];
        q_sh[r][c4 + 0] = qv.x; q_sh[r][c4 + 1] = qv.y;
        q_sh[r][c4 + 2] = qv.z; q_sh[r][c4 + 3] = qv.w;
    }
    if (tid < 128) ksum_sh[tid] = ksum[bh * 128 + tid];
    if (tid < 32) {
        float idx = PIO2 * (float)(t0 + tid + 1) * (1.0f / Tt);
        s_sh[tid] = sinf(idx);
        c_sh[tid] = cosf(idx);
    }
    __syncthreads();

    if (tid < 32) {
        float ds = 0.0f, dc = 0.0f;
#pragma unroll 8
        for (int d = 0; d < 64; d++) {
            float qd = q_sh[tid][d];
            ds = fmaf(qd, ksum_sh[d], ds);
            dc = fmaf(qd, ksum_sh[64 + d], dc);
        }
        den_sh[tid] = s_sh[tid] * ds + c_sh[tid] * dc;
    }
    __syncthreads();

    int tl = tid & 31;
    int eb = tid >> 5;
    int e0 = eb * 8;
    float outs[8], outc[8];
#pragma unroll
    for (int j = 0; j < 8; j++) { outs[j] = 0.0f; outc[j] = 0.0f; }

#pragma unroll 4
    for (int d = 0; d < 64; d++) {
        float qd = q_sh[tl][d];
        float4 k0 = *(const float4*)&kv_sh[d][e0];
        float4 k1 = *(const float4*)&kv_sh[d][e0 + 4];
        float4 m0 = *(const float4*)&kv_sh[64 + d][e0];
        float4 m1 = *(const float4*)&kv_sh[64 + d][e0 + 4];
        outs[0]=fmaf(qd,k0.x,outs[0]); outs[1]=fmaf(qd,k0.y,outs[1]);
        outs[2]=fmaf(qd,k0.z,outs[2]); outs[3]=fmaf(qd,k0.w,outs[3]);
        outs[4]=fmaf(qd,k1.x,outs[4]); outs[5]=fmaf(qd,k1.y,outs[5]);
        outs[6]=fmaf(qd,k1.z,outs[6]); outs[7]=fmaf(qd,k1.w,outs[7]);
        outc[0]=fmaf(qd,m0.x,outc[0]); outc[1]=fmaf(qd,m0.y,outc[1]);
        outc[2]=fmaf(qd,m0.z,outc[2]); outc[3]=fmaf(qd,m0.w,outc[3]);
        outc[4]=fmaf(qd,m1.x,outc[4]); outc[5]=fmaf(qd,m1.y,outc[5]);
        outc[6]=fmaf(qd,m1.z,outc[6]); outc[7]=fmaf(qd,m1.w,outc[7]);
    }
    float z = 1.0f / fmaxf(den_sh[tl], 1e-6f);
    float s = s_sh[tl] * z, c = c_sh[tl] * z;
    float o[8];
#pragma unroll
    for (int j = 0; j < 8; j++) o[j] = s * outs[j] + c * outc[j];
    uint32_t hp[4], lp[4];
#pragma unroll
    for (int j = 0; j < 8; j += 2) split2(o[j], o[j+1], hp[j>>1], lp[j>>1]);
    size_t off = (size_t)(b * Tt + t0 + tl) * Ee + h * 64 + e0;
    *(uint4*)&Ohi[off] = make_uint4(hp[0], hp[1], hp[2], hp[3]);
    *(uint4*)&Olo[off] = make_uint4(lp[0], lp[1], lp[2], lp[3]);
}

// ===================== launch =====================
extern "C" void kernel_launch(void* const* d_in, const int* in_sizes, int n_in,
                              void* d_out, int out_size) {
    const float* x      = (const float*)d_in[0];
    const float* ln1_w  = (const float*)d_in[1];
    const float* ln1_b  = (const float*)d_in[2];
    const float* wq     = (const float*)d_in[3];
    const float* bq     = (const float*)d_in[4];
    const float* wk     = (const float*)d_in[5];
    const float* bk     = (const float*)d_in[6];
    const float* wv     = (const float*)d_in[7];
    const float* bv     = (const float*)d_in[8];
    const float* wo     = (const float*)d_in[9];
    const float* bo     = (const float*)d_in[10];
    const float* ln2_w  = (const float*)d_in[11];
    const float* ln2_b  = (const float*)d_in[12];
    const float* w_fc   = (const float*)d_in[13];
    const float* b_fc   = (const float*)d_in[14];
    const float* w_proj = (const float*)d_in[15];
    const float* b_proj = (const float*)d_in[16];
    float* out = (float*)d_out;

    __nv_bfloat16 *p_h_hi, *p_h_lo, *p_attn_hi, *p_attn_lo, *p_fc_hi, *p_fc_lo;
    __nv_bfloat16 *p_wq_hi, *p_wq_lo, *p_wk_hi, *p_wk_lo, *p_wv_hi, *p_wv_lo;
    __nv_bfloat16 *p_wo_hi, *p_wo_lo, *p_wfc_hi, *p_wfc_lo, *p_wpj_hi, *p_wpj_lo;
    float *p_q, *p_k, *p_v, *p_x2, *p_kv, *p_ksum;
    cudaGetSymbolAddress((void**)&p_h_hi,    g_h_hi);
    cudaGetSymbolAddress((void**)&p_h_lo,    g_h_lo);
    cudaGetSymbolAddress((void**)&p_attn_hi, g_attn_hi);
    cudaGetSymbolAddress((void**)&p_attn_lo, g_attn_lo);
    cudaGetSymbolAddress((void**)&p_fc_hi,   g_fc_hi);
    cudaGetSymbolAddress((void**)&p_fc_lo,   g_fc_lo);
    cudaGetSymbolAddress((void**)&p_wq_hi,   g_wq_hi);
    cudaGetSymbolAddress((void**)&p_wq_lo,   g_wq_lo);
    cudaGetSymbolAddress((void**)&p_wk_hi,   g_wk_hi);
    cudaGetSymbolAddress((void**)&p_wk_lo,   g_wk_lo);
    cudaGetSymbolAddress((void**)&p_wv_hi,   g_wv_hi);
    cudaGetSymbolAddress((void**)&p_wv_lo,   g_wv_lo);
    cudaGetSymbolAddress((void**)&p_wo_hi,   g_wo_hi);
    cudaGetSymbolAddress((void**)&p_wo_lo,   g_wo_lo);
    cudaGetSymbolAddress((void**)&p_wfc_hi,  g_wfc_hi);
    cudaGetSymbolAddress((void**)&p_wfc_lo,  g_wfc_lo);
    cudaGetSymbolAddress((void**)&p_wpj_hi,  g_wpj_hi);
    cudaGetSymbolAddress((void**)&p_wpj_lo,  g_wpj_lo);
    cudaGetSymbolAddress((void**)&p_q,    g_q);
    cudaGetSymbolAddress((void**)&p_k,    g_k);
    cudaGetSymbolAddress((void**)&p_v,    g_v);
    cudaGetSymbolAddress((void**)&p_x2,   g_x2);
    cudaGetSymbolAddress((void**)&p_kv,   g_kv);
    cudaGetSymbolAddress((void**)&p_ksum, g_ksum);

    cudaFuncSetAttribute(gemm_mma<1, false, 0>, cudaFuncAttributeMaxDynamicSharedMemorySize, GT_SMEM);
    cudaFuncSetAttribute(gemm_mma<0, false, 0>, cudaFuncAttributeMaxDynamicSharedMemorySize, GT_SMEM);
    cudaFuncSetAttribute(gemm_mma<0, true,  0>, cudaFuncAttributeMaxDynamicSharedMemorySize, GT_SMEM);
    cudaFuncSetAttribute(gemm_mma<2, false, 1>, cudaFuncAttributeMaxDynamicSharedMemorySize, GT_SMEM);

    // 0. weight transposes + splits
    transpose_split_kernel<<<dim3(Ee/32, Ee/32), 256>>>(wq,     p_wq_hi,  p_wq_lo,  Ee, Ee);
    transpose_split_kernel<<<dim3(Ee/32, Ee/32), 256>>>(wk,     p_wk_hi,  p_wk_lo,  Ee, Ee);
    transpose_split_kernel<<<dim3(Ee/32, Ee/32), 256>>>(wv,     p_wv_hi,  p_wv_lo,  Ee, Ee);
    transpose_split_kernel<<<dim3(Ee/32, Ee/32), 256>>>(wo,     p_wo_hi,  p_wo_lo,  Ee, Ee);
    transpose_split_kernel<<<dim3(FF/32, Ee/32), 256>>>(w_fc,   p_wfc_hi, p_wfc_lo, Ee, FF);
    transpose_split_kernel<<<dim3(Ee/32, FF/32), 256>>>(w_proj, p_wpj_hi, p_wpj_lo, FF, Ee);

    // 1. h = LN1(x)  (bf16 hi/lo)
    ln_kernel<<<M_ROWS, 256>>>(x, ln1_w, ln1_b, p_h_hi, p_h_lo);

    // 2-4. q,k,v projections (tensor cores via mma.sync)
    dim3 g1(Ee / 128, M_ROWS / 128);
    gemm_mma<1, false, 0><<<g1, 256, GT_SMEM>>>(p_h_hi, p_h_lo, p_wq_hi, p_wq_lo,
        bq, nullptr, p_q, nullptr, nullptr, M_ROWS, Ee, Ee);
    gemm_mma<1, false, 0><<<g1, 256, GT_SMEM>>>(p_h_hi, p_h_lo, p_wk_hi, p_wk_lo,
        bk, nullptr, p_k, nullptr, nullptr, M_ROWS, Ee, Ee);
    gemm_mma<0, false, 0><<<g1, 256, GT_SMEM>>>(p_h_hi, p_h_lo, p_wv_hi, p_wv_lo,
        bv, nullptr, p_v, nullptr, nullptr, M_ROWS, Ee, Ee);

    // 5-6. kv / ksum reduction
    zero_kernel<<<(Bb*Hh*128*Dd + 255) / 256, 256>>>(p_kv, Bb*Hh*128*Dd);
    zero_kernel<<<(Bb*Hh*128 + 255) / 256, 256>>>(p_ksum, Bb*Hh*128);
    kv_kernel<<<dim3(Bb * Hh, TSPLIT), 256>>>(p_k, p_v, p_kv, p_ksum);

    // 7. attention output (bf16 hi/lo)
    attn_kernel<<<dim3(Tt / 32, Bb * Hh), 256>>>(p_q, p_kv, p_ksum, p_attn_hi, p_attn_lo);

    // 8. x2 = x + attn @ wo + bo
    gemm_mma<0, true, 0><<<g1, 256, GT_SMEM>>>(p_attn_hi, p_attn_lo, p_wo_hi, p_wo_lo,
        bo, x, p_x2, nullptr, nullptr, M_ROWS, Ee, Ee);

    // 9. h = LN2(x2)
    ln_kernel<<<M_ROWS, 256>>>(p_x2, ln2_w, ln2_b, p_h_hi, p_h_lo);

    // 10. fc = gelu(h @ w_fc + b_fc) (bf16 hi/lo)
    dim3 g2(FF / 128, M_ROWS / 128);
    gemm_mma<2, false, 1><<<g2, 256, GT_SMEM>>>(p_h_hi, p_h_lo, p_wfc_hi, p_wfc_lo,
        b_fc, nullptr, nullptr, p_fc_hi, p_fc_lo, M_ROWS, FF, Ee);

    // 11. out = x2 + fc @ w_proj + b_proj
    gemm_mma<0, true, 0><<<g1, 256, GT_SMEM>>>(p_fc_hi, p_fc_lo, p_wpj_hi, p_wpj_lo,
        b_proj, p_x2, out, nullptr, nullptr, M_ROWS, Ee, FF);
}

// round 4
// speedup vs baseline: 3.0200x; 1.5303x over previous
#include <cuda_runtime.h>
#include <cuda_bf16.h>
#include <math.h>
#include <stdint.h>

#define Bb 4
#define Tt 4096
#define Ee 1024
#define Hh 16
#define Dd 64
#define M_ROWS (Bb*Tt)          // 16384
#define FF (4*Ee)               // 4096
#define PIO2 1.5707963267948966f

// ===================== PTX helpers (baseline ISA only) =====================
__device__ __forceinline__ uint32_t smem_to_u32(const void* p) {
    uint32_t a;
    asm("{ .reg .u64 t; cvta.to.shared.u64 t, %1; cvt.u32.u64 %0, t; }" : "=r"(a) : "l"(p));
    return a;
}
#define CP_ASYNC16(saddr, gptr) \
    asm volatile("cp.async.cg.shared.global [%0], [%1], 16;" :: "r"(saddr), "l"(gptr))
#define CP_COMMIT() asm volatile("cp.async.commit_group;" ::: "memory")
#define CP_WAIT1()  asm volatile("cp.async.wait_group 1;" ::: "memory")

#define LDSM_X4(r0,r1,r2,r3, addr) \
    asm volatile("ldmatrix.sync.aligned.m8n8.x4.shared.b16 {%0,%1,%2,%3}, [%4];" \
        : "=r"(r0),"=r"(r1),"=r"(r2),"=r"(r3) : "r"(addr))

#define MMA_BF16(d, a, b) \
    asm volatile("mma.sync.aligned.m16n8k16.row.col.f32.bf16.bf16.f32 " \
        "{%0,%1,%2,%3}, {%4,%5,%6,%7}, {%8,%9}, {%0,%1,%2,%3};" \
        : "+f"((d)[0]),"+f"((d)[1]),"+f"((d)[2]),"+f"((d)[3]) \
        : "r"((a)[0]),"r"((a)[1]),"r"((a)[2]),"r"((a)[3]), "r"((b)[0]),"r"((b)[1]))

__device__ __forceinline__ void split2(float a, float b, uint32_t& hp, uint32_t& lp) {
    __nv_bfloat16 ha = __float2bfloat16(a), hb = __float2bfloat16(b);
    __nv_bfloat16 la = __float2bfloat16(a - __bfloat162float(ha));
    __nv_bfloat16 lb = __float2bfloat16(b - __bfloat162float(hb));
    hp = (uint32_t)__bfloat16_as_ushort(ha) | ((uint32_t)__bfloat16_as_ushort(hb) << 16);
    lp = (uint32_t)__bfloat16_as_ushort(la) | ((uint32_t)__bfloat16_as_ushort(lb) << 16);
}

// ===================== scratch (device globals) =====================
__device__ __nv_bfloat16 g_h_hi   [M_ROWS*Ee];
__device__ __nv_bfloat16 g_h_lo   [M_ROWS*Ee];
__device__ __nv_bfloat16 g_attn_hi[M_ROWS*Ee];
__device__ __nv_bfloat16 g_attn_lo[M_ROWS*Ee];
__device__ __nv_bfloat16 g_fc_hi  [(size_t)M_ROWS*FF];
__device__ __nv_bfloat16 g_fc_lo  [(size_t)M_ROWS*FF];
__device__ float g_q [M_ROWS*Ee];
__device__ float g_k [M_ROWS*Ee];
__device__ float g_v [M_ROWS*Ee];
__device__ float g_x2[M_ROWS*Ee];
__device__ float g_kv  [Bb*Hh*128*Dd];
__device__ float g_ksum[Bb*Hh*128];
__device__ float g_bqkv[3*Ee];
// transposed split weights: [N, K] bf16
__device__ __nv_bfloat16 g_wqkv_hi[3*Ee*Ee], g_wqkv_lo[3*Ee*Ee];   // q|k|v stacked in N
__device__ __nv_bfloat16 g_wo_hi[Ee*Ee],  g_wo_lo[Ee*Ee];
__device__ __nv_bfloat16 g_wfc_hi[(size_t)FF*Ee], g_wfc_lo[(size_t)FF*Ee];
__device__ __nv_bfloat16 g_wpj_hi[(size_t)Ee*FF], g_wpj_lo[(size_t)Ee*FF];

// ===================== transpose + split: W[K,N] -> T_hi/lo[N,K] ===========
__global__ void transpose_split_kernel(const float* __restrict__ W,
                                       __nv_bfloat16* __restrict__ Th,
                                       __nv_bfloat16* __restrict__ Tl, int K, int N) {
    __shared__ float ts[32][33];
    int n0 = blockIdx.x * 32, k0 = blockIdx.y * 32;
    int tx = threadIdx.x & 31, ty = threadIdx.x >> 5;
#pragma unroll
    for (int i = 0; i < 32; i += 8)
        ts[ty + i][tx] = W[(size_t)(k0 + ty + i) * N + n0 + tx];
    __syncthreads();
#pragma unroll
    for (int i = 0; i < 32; i += 8) {
        float v = ts[tx][ty + i];
        __nv_bfloat16 h = __float2bfloat16(v);
        __nv_bfloat16 l = __float2bfloat16(v - __bfloat162float(h));
        size_t off = (size_t)(n0 + ty + i) * K + k0 + tx;
        Th[off] = h;
        Tl[off] = l;
    }
}

__global__ void concat_bias_kernel(const float* __restrict__ a, const float* __restrict__ b,
                                   const float* __restrict__ c, float* __restrict__ o) {
    int i = blockIdx.x * 256 + threadIdx.x;
    if (i < Ee) o[i] = a[i];
    else if (i < 2 * Ee) o[i] = b[i - Ee];
    else o[i] = c[i - 2 * Ee];
}

// ===================== LayerNorm -> bf16 hi/lo =====================
__global__ void ln_kernel(const float* __restrict__ X, const float* __restrict__ w,
                          const float* __restrict__ b,
                          __nv_bfloat16* __restrict__ Yhi, __nv_bfloat16* __restrict__ Ylo) {
    int row = blockIdx.x;
    int tid = threadIdx.x;                 // 256 threads
    const float4* x4 = (const float4*)(X + (size_t)row * Ee);
    float4 v = x4[tid];
    __shared__ float red[8];

    float s = v.x + v.y + v.z + v.w;
    for (int o = 16; o > 0; o >>= 1) s += __shfl_down_sync(0xffffffffu, s, o);
    if ((tid & 31) == 0) red[tid >> 5] = s;
    __syncthreads();
    if (tid < 8) {
        float t = red[tid];
        for (int o = 4; o > 0; o >>= 1) t += __shfl_down_sync(0xffu, t, o);
        if (tid == 0) red[0] = t;
    }
    __syncthreads();
    float mu = red[0] * (1.0f / Ee);
    __syncthreads();

    float dx = v.x - mu, dy = v.y - mu, dz = v.z - mu, dw = v.w - mu;
    float ss = dx*dx + dy*dy + dz*dz + dw*dw;
    for (int o = 16; o > 0; o >>= 1) ss += __shfl_down_sync(0xffffffffu, ss, o);
    if ((tid & 31) == 0) red[tid >> 5] = ss;
    __syncthreads();
    if (tid < 8) {
        float t = red[tid];
        for (int o = 4; o > 0; o >>= 1) t += __shfl_down_sync(0xffu, t, o);
        if (tid == 0) red[0] = t;
    }
    __syncthreads();
    float rstd = rsqrtf(red[0] * (1.0f / Ee) + 1e-5f);

    float4 wv = ((const float4*)w)[tid];
    float4 bv = ((const float4*)b)[tid];
    float ox = dx * rstd * wv.x + bv.x;
    float oy = dy * rstd * wv.y + bv.y;
    float oz = dz * rstd * wv.z + bv.z;
    float ow = dw * rstd * wv.w + bv.w;
    uint32_t h0, l0, h1, l1;
    split2(ox, oy, h0, l0);
    split2(oz, ow, h1, l1);
    size_t off = (size_t)row * Ee + tid * 4;
    *(uint2*)&Yhi[off] = make_uint2(h0, h1);
    *(uint2*)&Ylo[off] = make_uint2(l0, l1);
}

// ===================== mma.sync split-bf16 GEMM ============================
// Tile 128x128, K-chunk 64, 3-stage cp.async pipeline.
// ACT: 0 none, 1 relu, 2 gelu, 3 fused-QKV (relu for sections 0,1; split outputs).
// OSPLIT: 0 -> fp32, 1 -> bf16 hi/lo pair.
#define STAGE_BYTES 65536
#define GT_SMEM (3*STAGE_BYTES)

__device__ __forceinline__ void load_stage(
    uint32_t sbase, int slot, int tid, int m0, int n0, int k0, int K,
    const __nv_bfloat16* Ahi, const __nv_bfloat16* Alo,
    const __nv_bfloat16* Bhi, const __nv_bfloat16* Blo)
{
    uint32_t sb = sbase + slot * STAGE_BYTES;
#pragma unroll
    for (int i = 0; i < 4; i++) {
        int u = tid + i * 256;        // 0..1023
        int r = u >> 3, s = u & 7;
        uint32_t soff = (uint32_t)(r * 128) + (uint32_t)(((s ^ (r & 7)) << 4));
        size_t gA = (size_t)(m0 + r) * K + k0 + s * 8;
        size_t gB = (size_t)(n0 + r) * K + k0 + s * 8;
        CP_ASYNC16(sb + soff,         Ahi + gA);
        CP_ASYNC16(sb + 16384 + soff, Alo + gA);
        CP_ASYNC16(sb + 32768 + soff, Bhi + gB);
        CP_ASYNC16(sb + 49152 + soff, Blo + gB);
    }
}

template<int ACT, bool RES, int OSPLIT>
__global__ __launch_bounds__(256, 1) void gemm_mma(
    const __nv_bfloat16* __restrict__ Ahi, const __nv_bfloat16* __restrict__ Alo,
    const __nv_bfloat16* __restrict__ Bhi, const __nv_bfloat16* __restrict__ Blo,
    const float* __restrict__ bias, const float* __restrict__ res,
    float* __restrict__ Cf, float* __restrict__ Cf2, float* __restrict__ Cf3,
    __nv_bfloat16* __restrict__ Chi, __nv_bfloat16* __restrict__ Clo,
    int M, int N, int K)
{
    extern __shared__ char smem[];
    uint32_t sbase = smem_to_u32(smem);
    int tid = threadIdx.x;
    int wid = tid >> 5, l = tid & 31;
    int warpM = wid >> 2, warpN = wid & 3;     // 2 x 4 warps, warp tile 64x32
    int m0 = blockIdx.y * 128, n0 = blockIdx.x * 128;

    int g = l & 7, grp = l >> 3;
    uint32_t constA = (uint32_t)((warpM * 64 + (grp & 1) * 8 + g) * 128);
    int khA = grp >> 1;
    uint32_t constB = (uint32_t)((warpN * 32 + (grp >> 1) * 8 + g) * 128);
    int khB = grp & 1;

    float acc[4][4][4];
#pragma unroll
    for (int mi = 0; mi < 4; mi++)
#pragma unroll
        for (int ni = 0; ni < 4; ni++)
#pragma unroll
            for (int j = 0; j < 4; j++) acc[mi][ni][j] = 0.0f;

    const int NC = K >> 6;
    load_stage(sbase, 0, tid, m0, n0, 0, K, Ahi, Alo, Bhi, Blo);
    CP_COMMIT();
    load_stage(sbase, 1, tid, m0, n0, 64, K, Ahi, Alo, Bhi, Blo);
    CP_COMMIT();

    int slot = 0, nslot = 2;
    for (int c = 0; c < NC; c++) {
        CP_WAIT1();                 // group c complete (<=1 newest outstanding)
        __syncthreads();            // visibility + all warps done with slot nslot's old data
        if (c + 2 < NC)
            load_stage(sbase, nslot, tid, m0, n0, (c + 2) * 64, K, Ahi, Alo, Bhi, Blo);
        CP_COMMIT();
        uint32_t sA = sbase + slot * STAGE_BYTES;
        uint32_t sB = sA + 32768;
#pragma unroll
        for (int ks = 0; ks < 4; ks++) {
            uint32_t Ah[4][4], Al4[4][4], Bh[4][2], Bl[4][2];
            uint32_t segA = (uint32_t)(((ks * 2 + khA) ^ g) << 4);
            uint32_t segB = (uint32_t)(((ks * 2 + khB) ^ g) << 4);
#pragma unroll
            for (int mi = 0; mi < 4; mi++) {
                uint32_t ad = sA + constA + mi * 2048 + segA;
                LDSM_X4(Ah[mi][0], Ah[mi][1], Ah[mi][2], Ah[mi][3], ad);
                LDSM_X4(Al4[mi][0], Al4[mi][1], Al4[mi][2], Al4[mi][3], ad + 16384);
            }
#pragma unroll
            for (int np = 0; np < 2; np++) {
                uint32_t bd = sB + constB + np * 2048 + segB;
                uint32_t t0, t1, t2, t3;
                LDSM_X4(t0, t1, t2, t3, bd);
                Bh[np*2][0] = t0; Bh[np*2][1] = t1; Bh[np*2+1][0] = t2; Bh[np*2+1][1] = t3;
                LDSM_X4(t0, t1, t2, t3, bd + 16384);
                Bl[np*2][0] = t0; Bl[np*2][1] = t1; Bl[np*2+1][0] = t2; Bl[np*2+1][1] = t3;
            }
            // pass-outermost: each accumulator reused at distance 16 MMAs
#pragma unroll
            for (int mi = 0; mi < 4; mi++)
#pragma unroll
                for (int ni = 0; ni < 4; ni++)
                    MMA_BF16(acc[mi][ni], Ah[mi], Bh[ni]);
#pragma unroll
            for (int mi = 0; mi < 4; mi++)
#pragma unroll
                for (int ni = 0; ni < 4; ni++)
                    MMA_BF16(acc[mi][ni], Ah[mi], Bl[ni]);
#pragma unroll
            for (int mi = 0; mi < 4; mi++)
#pragma unroll
                for (int ni = 0; ni < 4; ni++)
                    MMA_BF16(acc[mi][ni], Al4[mi], Bh[ni]);
        }
        __syncthreads();
        slot = slot == 2 ? 0 : slot + 1;
        nslot = nslot == 2 ? 0 : nslot + 1;
    }

    // ---------------- epilogue ----------------
    int sec = n0 >> 10;                       // for ACT3 (uniform per CTA)
    float* dst3 = (ACT == 3) ? (sec == 0 ? Cf : (sec == 1 ? Cf2 : Cf3)) : Cf;
#pragma unroll
    for (int mi = 0; mi < 4; mi++) {
#pragma unroll
        for (int half = 0; half < 2; half++) {
            int m = m0 + warpM * 64 + mi * 16 + (l >> 2) + half * 8;
#pragma unroll
            for (int ni = 0; ni < 4; ni++) {
                int n = n0 + warpN * 32 + ni * 8 + (l & 3) * 2;
                float v0 = acc[mi][ni][half * 2 + 0];
                float v1 = acc[mi][ni][half * 2 + 1];
                float2 bz = __ldg((const float2*)&bias[n]);
                v0 += bz.x; v1 += bz.y;
                if (ACT == 1 || (ACT == 3 && sec < 2)) {
                    v0 = fmaxf(v0, 0.0f); v1 = fmaxf(v1, 0.0f);
                } else if (ACT == 2) {
                    v0 = 0.5f * v0 * (1.0f + erff(v0 * 0.70710678118654752f));
                    v1 = 0.5f * v1 * (1.0f + erff(v1 * 0.70710678118654752f));
                }
                if (ACT == 3) {
                    size_t off = (size_t)m * Ee + (n - (sec << 10));
                    *(float2*)&dst3[off] = make_float2(v0, v1);
                } else {
                    size_t off = (size_t)m * N + n;
                    if (RES) {
                        float2 rv = *(const float2*)&res[off];
                        v0 += rv.x; v1 += rv.y;
                    }
                    if (OSPLIT == 0) {
                        *(float2*)&Cf[off] = make_float2(v0, v1);
                    } else {
                        uint32_t hp, lp;
                        split2(v0, v1, hp, lp);
                        *(uint32_t*)&Chi[off] = hp;
                        *(uint32_t*)&Clo[off] = lp;
                    }
                }
            }
        }
    }
}

// ===================== zero =====================
__global__ void zero_kernel(float* p, int n) {
    int i = blockIdx.x * blockDim.x + threadIdx.x;
    if (i < n) p[i] = 0.0f;
}

// ===================== kv reduction =====================
#define TSPLIT 4
__global__ __launch_bounds__(256) void kv_kernel(
    const float* __restrict__ Kp, const float* __restrict__ Vp,
    float* __restrict__ kv, float* __restrict__ ksum)
{
    int bh = blockIdx.x;
    int b = bh >> 4, h = bh & 15;
    int tid = threadIdx.x;
    __shared__ float ks_sh[32][64];
    __shared__ float vs_sh[32][64];
    __shared__ float s_sh[32], c_sh[32];

    int dd = tid & 63;
    int eb = tid >> 6;
    int e0 = eb * 16;
    float acc_s[16], acc_c[16];
#pragma unroll
    for (int i = 0; i < 16; i++) { acc_s[i] = 0.0f; acc_c[i] = 0.0f; }
    float ksum_s = 0.0f, ksum_c = 0.0f;

    int tbase = blockIdx.y * (Tt / TSPLIT);
    for (int tt = 0; tt < Tt / TSPLIT; tt += 32) {
        int t0 = tbase + tt;
#pragma unroll
        for (int ld = 0; ld < 2; ld++) {
            int id = tid + ld * 256;
            int r = id >> 4, c4 = (id & 15) * 4;
            size_t off = (size_t)(b * Tt + t0 + r) * Ee + h * 64 + c4;
            *(float4*)&ks_sh[r][c4] = *(const float4*)&Kp[off];
            *(float4*)&vs_sh[r][c4] = *(const float4*)&Vp[off];
        }
        if (tid < 32) {
            float idx = PIO2 * (float)(t0 + tid + 1) * (1.0f / Tt);
            s_sh[tid] = sinf(idx);
            c_sh[tid] = cosf(idx);
        }
        __syncthreads();
#pragma unroll 4
        for (int r = 0; r < 32; r++) {
            float kd = ks_sh[r][dd];
            float as = kd * s_sh[r];
            float ac = kd * c_sh[r];
            if (eb == 0) { ksum_s += as; ksum_c += ac; }
#pragma unroll
            for (int i = 0; i < 16; i++) {
                float ve = vs_sh[r][e0 + i];
                acc_s[i] = fmaf(as, ve, acc_s[i]);
                acc_c[i] = fmaf(ac, ve, acc_c[i]);
            }
        }
        __syncthreads();
    }
    float* kvb = kv + (size_t)bh * 128 * Dd;
#pragma unroll
    for (int i = 0; i < 16; i++) {
        atomicAdd(&kvb[dd * Dd + e0 + i], acc_s[i]);
        atomicAdd(&kvb[(64 + dd) * Dd + e0 + i], acc_c[i]);
    }
    if (eb == 0) {
        atomicAdd(&ksum[bh * 128 + dd], ksum_s);
        atomicAdd(&ksum[bh * 128 + 64 + dd], ksum_c);
    }
}

// ===================== attention: out -> bf16 hi/lo =====================
__global__ __launch_bounds__(256) void attn_kernel(
    const float* __restrict__ Qp, const float* __restrict__ kv,
    const float* __restrict__ ksum,
    __nv_bfloat16* __restrict__ Ohi, __nv_bfloat16* __restrict__ Olo)
{
    int bh = blockIdx.y;
    int b = bh >> 4, h = bh & 15;
    int t0 = blockIdx.x * 32;
    int tid = threadIdx.x;

    __shared__ float kv_sh[128][64];
    __shared__ float q_sh[32][65];
    __shared__ float ksum_sh[128];
    __shared__ float den_sh[32], s_sh[32], c_sh[32];

#pragma unroll
    for (int ld = 0; ld < 8; ld++) {
        int id = tid + ld * 256;
        int r = id >> 4, c4 = (id & 15) * 4;
        *(float4*)&kv_sh[r][c4] = *(const float4*)&kv[((size_t)bh * 128 + r) * Dd + c4];
    }
#pragma unroll
    for (int ld = 0; ld < 2; ld++) {
        int id = tid + ld * 256;
        int r = id >> 4, c4 = (id & 15) * 4;
        float4 qv = *(const float4*)&Qp[(size_t)(b * Tt + t0 + r) * Ee + h * 64 + c4];
        q_sh[r][c4 + 0] = qv.x; q_sh[r][c4 + 1] = qv.y;
        q_sh[r][c4 + 2] = qv.z; q_sh[r][c4 + 3] = qv.w;
    }
    if (tid < 128) ksum_sh[tid] = ksum[bh * 128 + tid];
    if (tid < 32) {
        float idx = PIO2 * (float)(t0 + tid + 1) * (1.0f / Tt);
        s_sh[tid] = sinf(idx);
        c_sh[tid] = cosf(idx);
    }
    __syncthreads();

    if (tid < 32) {
        float ds = 0.0f, dc = 0.0f;
#pragma unroll 8
        for (int d = 0; d < 64; d++) {
            float qd = q_sh[tid][d];
            ds = fmaf(qd, ksum_sh[d], ds);
            dc = fmaf(qd, ksum_sh[64 + d], dc);
        }
        den_sh[tid] = s_sh[tid] * ds + c_sh[tid] * dc;
    }
    __syncthreads();

    int tl = tid & 31;
    int eb = tid >> 5;
    int e0 = eb * 8;
    float outs[8], outc[8];
#pragma unroll
    for (int j = 0; j < 8; j++) { outs[j] = 0.0f; outc[j] = 0.0f; }

#pragma unroll 4
    for (int d = 0; d < 64; d++) {
        float qd = q_sh[tl][d];
        float4 k0 = *(const float4*)&kv_sh[d][e0];
        float4 k1 = *(const float4*)&kv_sh[d][e0 + 4];
        float4 m0 = *(const float4*)&kv_sh[64 + d][e0];
        float4 m1 = *(const float4*)&kv_sh[64 + d][e0 + 4];
        outs[0]=fmaf(qd,k0.x,outs[0]); outs[1]=fmaf(qd,k0.y,outs[1]);
        outs[2]=fmaf(qd,k0.z,outs[2]); outs[3]=fmaf(qd,k0.w,outs[3]);
        outs[4]=fmaf(qd,k1.x,outs[4]); outs[5]=fmaf(qd,k1.y,outs[5]);
        outs[6]=fmaf(qd,k1.z,outs[6]); outs[7]=fmaf(qd,k1.w,outs[7]);
        outc[0]=fmaf(qd,m0.x,outc[0]); outc[1]=fmaf(qd,m0.y,outc[1]);
        outc[2]=fmaf(qd,m0.z,outc[2]); outc[3]=fmaf(qd,m0.w,outc[3]);
        outc[4]=fmaf(qd,m1.x,outc[4]); outc[5]=fmaf(qd,m1.y,outc[5]);
        outc[6]=fmaf(qd,m1.z,outc[6]); outc[7]=fmaf(qd,m1.w,outc[7]);
    }
    float z = 1.0f / fmaxf(den_sh[tl], 1e-6f);
    float s = s_sh[tl] * z, c = c_sh[tl] * z;
    float o[8];
#pragma unroll
    for (int j = 0; j < 8; j++) o[j] = s * outs[j] + c * outc[j];
    uint32_t hp[4], lp[4];
#pragma unroll
    for (int j = 0; j < 8; j += 2) split2(o[j], o[j+1], hp[j>>1], lp[j>>1]);
    size_t off = (size_t)(b * Tt + t0 + tl) * Ee + h * 64 + e0;
    *(uint4*)&Ohi[off] = make_uint4(hp[0], hp[1], hp[2], hp[3]);
    *(uint4*)&Olo[off] = make_uint4(lp[0], lp[1], lp[2], lp[3]);
}

// ===================== launch =====================
extern "C" void kernel_launch(void* const* d_in, const int* in_sizes, int n_in,
                              void* d_out, int out_size) {
    const float* x      = (const float*)d_in[0];
    const float* ln1_w  = (const float*)d_in[1];
    const float* ln1_b  = (const float*)d_in[2];
    const float* wq     = (const float*)d_in[3];
    const float* bq     = (const float*)d_in[4];
    const float* wk     = (const float*)d_in[5];
    const float* bk     = (const float*)d_in[6];
    const float* wv     = (const float*)d_in[7];
    const float* bv     = (const float*)d_in[8];
    const float* wo     = (const float*)d_in[9];
    const float* bo     = (const float*)d_in[10];
    const float* ln2_w  = (const float*)d_in[11];
    const float* ln2_b  = (const float*)d_in[12];
    const float* w_fc   = (const float*)d_in[13];
    const float* b_fc   = (const float*)d_in[14];
    const float* w_proj = (const float*)d_in[15];
    const float* b_proj = (const float*)d_in[16];
    float* out = (float*)d_out;

    __nv_bfloat16 *p_h_hi, *p_h_lo, *p_attn_hi, *p_attn_lo, *p_fc_hi, *p_fc_lo;
    __nv_bfloat16 *p_wqkv_hi, *p_wqkv_lo;
    __nv_bfloat16 *p_wo_hi, *p_wo_lo, *p_wfc_hi, *p_wfc_lo, *p_wpj_hi, *p_wpj_lo;
    float *p_q, *p_k, *p_v, *p_x2, *p_kv, *p_ksum, *p_bqkv;
    cudaGetSymbolAddress((void**)&p_h_hi,    g_h_hi);
    cudaGetSymbolAddress((void**)&p_h_lo,    g_h_lo);
    cudaGetSymbolAddress((void**)&p_attn_hi, g_attn_hi);
    cudaGetSymbolAddress((void**)&p_attn_lo, g_attn_lo);
    cudaGetSymbolAddress((void**)&p_fc_hi,   g_fc_hi);
    cudaGetSymbolAddress((void**)&p_fc_lo,   g_fc_lo);
    cudaGetSymbolAddress((void**)&p_wqkv_hi, g_wqkv_hi);
    cudaGetSymbolAddress((void**)&p_wqkv_lo, g_wqkv_lo);
    cudaGetSymbolAddress((void**)&p_wo_hi,   g_wo_hi);
    cudaGetSymbolAddress((void**)&p_wo_lo,   g_wo_lo);
    cudaGetSymbolAddress((void**)&p_wfc_hi,  g_wfc_hi);
    cudaGetSymbolAddress((void**)&p_wfc_lo,  g_wfc_lo);
    cudaGetSymbolAddress((void**)&p_wpj_hi,  g_wpj_hi);
    cudaGetSymbolAddress((void**)&p_wpj_lo,  g_wpj_lo);
    cudaGetSymbolAddress((void**)&p_q,    g_q);
    cudaGetSymbolAddress((void**)&p_k,    g_k);
    cudaGetSymbolAddress((void**)&p_v,    g_v);
    cudaGetSymbolAddress((void**)&p_x2,   g_x2);
    cudaGetSymbolAddress((void**)&p_kv,   g_kv);
    cudaGetSymbolAddress((void**)&p_ksum, g_ksum);
    cudaGetSymbolAddress((void**)&p_bqkv, g_bqkv);

    cudaFuncSetAttribute(gemm_mma<3, false, 0>, cudaFuncAttributeMaxDynamicSharedMemorySize, GT_SMEM);
    cudaFuncSetAttribute(gemm_mma<0, true,  0>, cudaFuncAttributeMaxDynamicSharedMemorySize, GT_SMEM);
    cudaFuncSetAttribute(gemm_mma<2, false, 1>, cudaFuncAttributeMaxDynamicSharedMemorySize, GT_SMEM);

    // launches 0-2: QKV weight transposes into stacked buffer
    transpose_split_kernel<<<dim3(Ee/32, Ee/32), 256>>>(wq, p_wqkv_hi,            p_wqkv_lo,            Ee, Ee);
    transpose_split_kernel<<<dim3(Ee/32, Ee/32), 256>>>(wk, p_wqkv_hi + Ee*Ee,    p_wqkv_lo + Ee*Ee,    Ee, Ee);
    transpose_split_kernel<<<dim3(Ee/32, Ee/32), 256>>>(wv, p_wqkv_hi + 2*Ee*Ee,  p_wqkv_lo + 2*Ee*Ee,  Ee, Ee);
    // launch 3: concat bias
    concat_bias_kernel<<<(3*Ee)/256, 256>>>(bq, bk, bv, p_bqkv);
    // launch 4: h = LN1(x)
    ln_kernel<<<M_ROWS, 256>>>(x, ln1_w, ln1_b, p_h_hi, p_h_lo);
    // launch 5 (ncu target): fused QKV GEMM, N=3072
    dim3 gqkv(3*Ee / 128, M_ROWS / 128);
    gemm_mma<3, false, 0><<<gqkv, 256, GT_SMEM>>>(p_h_hi, p_h_lo, p_wqkv_hi, p_wqkv_lo,
        p_bqkv, nullptr, p_q, p_k, p_v, nullptr, nullptr, M_ROWS, 3*Ee, Ee);

    // kv / ksum reduction
    zero_kernel<<<(Bb*Hh*128*Dd + 255) / 256, 256>>>(p_kv, Bb*Hh*128*Dd);
    zero_kernel<<<(Bb*Hh*128 + 255) / 256, 256>>>(p_ksum, Bb*Hh*128);
    kv_kernel<<<dim3(Bb * Hh, TSPLIT), 256>>>(p_k, p_v, p_kv, p_ksum);

    // attention output (bf16 hi/lo)
    attn_kernel<<<dim3(Tt / 32, Bb * Hh), 256>>>(p_q, p_kv, p_ksum, p_attn_hi, p_attn_lo);

    // x2 = x + attn @ wo + bo
    dim3 g1(Ee / 128, M_ROWS / 128);
    transpose_split_kernel<<<dim3(Ee/32, Ee/32), 256>>>(wo, p_wo_hi, p_wo_lo, Ee, Ee);
    gemm_mma<0, true, 0><<<g1, 256, GT_SMEM>>>(p_attn_hi, p_attn_lo, p_wo_hi, p_wo_lo,
        bo, x, p_x2, nullptr, nullptr, nullptr, nullptr, M_ROWS, Ee, Ee);

    // h = LN2(x2)
    ln_kernel<<<M_ROWS, 256>>>(p_x2, ln2_w, ln2_b, p_h_hi, p_h_lo);

    // fc = gelu(h @ w_fc + b_fc) (bf16 hi/lo)
    transpose_split_kernel<<<dim3(FF/32, Ee/32), 256>>>(w_fc, p_wfc_hi, p_wfc_lo, Ee, FF);
    dim3 g2(FF / 128, M_ROWS / 128);
    gemm_mma<2, false, 1><<<g2, 256, GT_SMEM>>>(p_h_hi, p_h_lo, p_wfc_hi, p_wfc_lo,
        b_fc, nullptr, nullptr, nullptr, nullptr, p_fc_hi, p_fc_lo, M_ROWS, FF, Ee);

    // out = x2 + fc @ w_proj + b_proj
    transpose_split_kernel<<<dim3(Ee/32, FF/32), 256>>>(w_proj, p_wpj_hi, p_wpj_lo, FF, Ee);
    gemm_mma<0, true, 0><<<g1, 256, GT_SMEM>>>(p_fc_hi, p_fc_lo, p_wpj_hi, p_wpj_lo,
        b_proj, p_x2, out, nullptr, nullptr, nullptr, nullptr, M_ROWS, Ee, FF);
}

// round 7
// speedup vs baseline: 3.9009x; 1.2917x over previous
#include <cuda_runtime.h>
#include <cuda_bf16.h>
#include <math.h>
#include <stdint.h>

#define Bb 4
#define Tt 4096
#define Ee 1024
#define Hh 16
#define Dd 64
#define M_ROWS (Bb*Tt)          // 16384
#define FF (4*Ee)               // 4096
#define PIO2 1.5707963267948966f

// ===================== PTX helpers (baseline ISA only) =====================
__device__ __forceinline__ uint32_t smem_to_u32(const void* p) {
    uint32_t a;
    asm("{ .reg .u64 t; cvta.to.shared.u64 t, %1; cvt.u32.u64 %0, t; }" : "=r"(a) : "l"(p));
    return a;
}
#define CP_ASYNC16(saddr, gptr) \
    asm volatile("cp.async.cg.shared.global [%0], [%1], 16;" :: "r"(saddr), "l"(gptr))
#define CP_COMMIT() asm volatile("cp.async.commit_group;" ::: "memory")
#define CP_WAIT1()  asm volatile("cp.async.wait_group 1;" ::: "memory")

#define LDSM_X4(r0,r1,r2,r3, addr) \
    asm volatile("ldmatrix.sync.aligned.m8n8.x4.shared.b16 {%0,%1,%2,%3}, [%4];" \
        : "=r"(r0),"=r"(r1),"=r"(r2),"=r"(r3) : "r"(addr))

#define MMA_TF32(d, a, b) \
    asm volatile("mma.sync.aligned.m16n8k8.row.col.f32.tf32.tf32.f32 " \
        "{%0,%1,%2,%3}, {%4,%5,%6,%7}, {%8,%9}, {%0,%1,%2,%3};" \
        : "+f"((d)[0]),"+f"((d)[1]),"+f"((d)[2]),"+f"((d)[3]) \
        : "r"((a)[0]),"r"((a)[1]),"r"((a)[2]),"r"((a)[3]), "r"((b)[0]),"r"((b)[1]))

__device__ __forceinline__ float to_tf32(float x) {
    float r;
    asm("cvt.rna.tf32.f32 %0, %1;" : "=f"(r) : "f"(x));
    return r;
}

// ===================== scratch (device globals) =====================
__device__ float g_h   [M_ROWS*Ee];           // LN out (tf32-rounded fp32)
__device__ float g_attn[M_ROWS*Ee];           // attn out (tf32-rounded)
__device__ float g_fc  [(size_t)M_ROWS*FF];   // gelu out (tf32-rounded)
__device__ float g_q [M_ROWS*Ee];
__device__ float g_k [M_ROWS*Ee];
__device__ float g_v [M_ROWS*Ee];
__device__ float g_x2[M_ROWS*Ee];
__device__ float g_kv  [Bb*Hh*128*Dd];
__device__ float g_ksum[Bb*Hh*128];
// transposed tf32-rounded weights: [N, K] fp32
__device__ float g_wqkv[3*Ee*Ee];             // q|k|v stacked in N
__device__ float g_wo  [Ee*Ee];
__device__ float g_wfc [(size_t)FF*Ee];
__device__ float g_wpj [(size_t)Ee*FF];

// ===================== transpose + tf32-round: W[K,N] -> T[N,K] ============
__global__ void transpose_tf32_kernel(const float* __restrict__ W,
                                      float* __restrict__ T, int K, int N) {
    __shared__ float ts[32][33];
    int n0 = blockIdx.x * 32, k0 = blockIdx.y * 32;
    int tx = threadIdx.x & 31, ty = threadIdx.x >> 5;
#pragma unroll
    for (int i = 0; i < 32; i += 8)
        ts[ty + i][tx] = W[(size_t)(k0 + ty + i) * N + n0 + tx];
    __syncthreads();
#pragma unroll
    for (int i = 0; i < 32; i += 8)
        T[(size_t)(n0 + ty + i) * K + k0 + tx] = to_tf32(ts[tx][ty + i]);
}

// all three QKV weights in one launch (blockIdx.z selects)
__global__ void transpose_qkv_kernel(const float* __restrict__ wq,
                                     const float* __restrict__ wk,
                                     const float* __restrict__ wv,
                                     float* __restrict__ T) {
    __shared__ float ts[32][33];
    const float* W = blockIdx.z == 0 ? wq : (blockIdx.z == 1 ? wk : wv);
    float* Tz = T + (size_t)blockIdx.z * Ee * Ee;
    int n0 = blockIdx.x * 32, k0 = blockIdx.y * 32;
    int tx = threadIdx.x & 31, ty = threadIdx.x >> 5;
#pragma unroll
    for (int i = 0; i < 32; i += 8)
        ts[ty + i][tx] = W[(size_t)(k0 + ty + i) * Ee + n0 + tx];
    __syncthreads();
#pragma unroll
    for (int i = 0; i < 32; i += 8)
        Tz[(size_t)(n0 + ty + i) * Ee + k0 + tx] = to_tf32(ts[tx][ty + i]);
}

// ===================== LayerNorm -> tf32-rounded fp32 =====================
__global__ void ln_kernel(const float* __restrict__ X, const float* __restrict__ w,
                          const float* __restrict__ b, float* __restrict__ Y) {
    int row = blockIdx.x;
    int tid = threadIdx.x;                 // 256 threads
    const float4* x4 = (const float4*)(X + (size_t)row * Ee);
    float4 v = x4[tid];
    __shared__ float red[8];

    float s = v.x + v.y + v.z + v.w;
    for (int o = 16; o > 0; o >>= 1) s += __shfl_down_sync(0xffffffffu, s, o);
    if ((tid & 31) == 0) red[tid >> 5] = s;
    __syncthreads();
    if (tid < 8) {
        float t = red[tid];
        for (int o = 4; o > 0; o >>= 1) t += __shfl_down_sync(0xffu, t, o);
        if (tid == 0) red[0] = t;
    }
    __syncthreads();
    float mu = red[0] * (1.0f / Ee);
    __syncthreads();

    float dx = v.x - mu, dy = v.y - mu, dz = v.z - mu, dw = v.w - mu;
    float ss = dx*dx + dy*dy + dz*dz + dw*dw;
    for (int o = 16; o > 0; o >>= 1) ss += __shfl_down_sync(0xffffffffu, ss, o);
    if ((tid & 31) == 0) red[tid >> 5] = ss;
    __syncthreads();
    if (tid < 8) {
        float t = red[tid];
        for (int o = 4; o > 0; o >>= 1) t += __shfl_down_sync(0xffu, t, o);
        if (tid == 0) red[0] = t;
    }
    __syncthreads();
    float rstd = rsqrtf(red[0] * (1.0f / Ee) + 1e-5f);

    float4 wv = ((const float4*)w)[tid];
    float4 bv = ((const float4*)b)[tid];
    float4 o;
    o.x = to_tf32(dx * rstd * wv.x + bv.x);
    o.y = to_tf32(dy * rstd * wv.y + bv.y);
    o.z = to_tf32(dz * rstd * wv.z + bv.z);
    o.w = to_tf32(dw * rstd * wv.w + bv.w);
    ((float4*)(Y + (size_t)row * Ee))[tid] = o;
}

// ===================== tf32 mma.sync GEMM ==================================
// C[m,n] = act( A[m,:] @ Bt[n,:]^T + bias[n] ) (+ res)
// A: [M,K] tf32-rounded fp32, Bt: [N,K] tf32-rounded fp32.
// Tile 128x128, K-chunk 64, 3-stage cp.async pipeline, 8 warps (warp 64x32).
// ACT: 0 none, 1 relu, 2 gelu(+tf32 out), 3 fused-QKV.
#define STAGE_BYTES 65536        // A 32KB + B 32KB (tf32 as fp32)
#define GT_SMEM (3*STAGE_BYTES)

__device__ __forceinline__ void load_stage(
    uint32_t sbase, int slot, int tid, int m0, int n0, int k0, int K,
    const float* A, const float* B)
{
    uint32_t sb = sbase + slot * STAGE_BYTES;
#pragma unroll
    for (int i = 0; i < 8; i++) {
        int u = tid + i * 256;        // 0..2047 16B-chunks
        int r = u >> 4, c = u & 15;
        uint32_t phys = (uint32_t)((c & 8) | ((c ^ (r & 7)) & 7));
        CP_ASYNC16(sb + r * 256 + phys * 16, A + (size_t)(m0 + r) * K + k0 + c * 4);
    }
#pragma unroll
    for (int i = 0; i < 8; i++) {
        int u = tid + i * 256;
        int r = u >> 4, c = u & 15;
        uint32_t phys = (uint32_t)((c & 8) | ((c ^ (r & 7)) & 7));
        CP_ASYNC16(sb + 32768 + r * 256 + phys * 16, B + (size_t)(n0 + r) * K + k0 + c * 4);
    }
}

template<int ACT, bool RES>
__global__ __launch_bounds__(256, 1) void gemm_tf32(
    const float* __restrict__ A, const float* __restrict__ Bt,
    const float* __restrict__ bias, const float* __restrict__ bias2,
    const float* __restrict__ bias3, const float* __restrict__ res,
    float* __restrict__ Cf, float* __restrict__ Cf2, float* __restrict__ Cf3,
    int M, int N, int K)
{
    extern __shared__ char smem[];
    uint32_t sbase = smem_to_u32(smem);
    int tid = threadIdx.x;
    int wid = tid >> 5, l = tid & 31;
    int warpM = wid >> 2, warpN = wid & 3;     // 2 x 4 warps, warp tile 64x32
    int m0 = blockIdx.y * 128, n0 = blockIdx.x * 128;

    // lane addressing for ldmatrix (b16-view of tf32 tiles)
    int xr = l & 7;                                   // swizzle xor (row&7 == l&7)
    int rowlaneA = (l & 7) + ((l >> 3) & 1) * 8;      // 0..15 within m16
    int chA = (l >> 4) & 1;                           // chunk low bit
    int rowlaneB = ((l >> 4) & 1) * 8 + (l & 7);      // 0..15 within n-pair
    int chB = (l >> 3) & 1;

    float acc[4][4][4];
#pragma unroll
    for (int mi = 0; mi < 4; mi++)
#pragma unroll
        for (int ni = 0; ni < 4; ni++)
#pragma unroll
            for (int j = 0; j < 4; j++) acc[mi][ni][j] = 0.0f;

    const int NC = K >> 6;
    load_stage(sbase, 0, tid, m0, n0, 0, K, A, Bt);
    CP_COMMIT();
    load_stage(sbase, 1, tid, m0, n0, 64, K, A, Bt);
    CP_COMMIT();

    int slot = 0, nslot = 2;
    for (int c = 0; c < NC; c++) {
        CP_WAIT1();
        __syncthreads();
        if (c + 2 < NC)
            load_stage(sbase, nslot, tid, m0, n0, (c + 2) * 64, K, A, Bt);
        CP_COMMIT();
        uint32_t sA = sbase + slot * STAGE_BYTES;
        uint32_t sB = sA + 32768;
#pragma unroll
        for (int k8 = 0; k8 < 8; k8++) {
            uint32_t Af[4][4], Bf[4][2];
            // A fragments: 4 x ldsm.x4
            {
                int cl = 2 * k8 + chA;
                uint32_t phys = (uint32_t)((cl & 8) | ((cl ^ xr) & 7));
#pragma unroll
                for (int mi = 0; mi < 4; mi++) {
                    uint32_t ad = sA + (uint32_t)((warpM * 64 + mi * 16 + rowlaneA) * 256) + phys * 16;
                    LDSM_X4(Af[mi][0], Af[mi][1], Af[mi][2], Af[mi][3], ad);
                }
            }
            // B fragments: 2 x ldsm.x4 (each covers an n8-pair)
            {
                int cl = 2 * k8 + chB;
                uint32_t phys = (uint32_t)((cl & 8) | ((cl ^ xr) & 7));
#pragma unroll
                for (int np = 0; np < 2; np++) {
                    uint32_t bd = sB + (uint32_t)((warpN * 32 + np * 16 + rowlaneB) * 256) + phys * 16;
                    uint32_t t0, t1, t2, t3;
                    LDSM_X4(t0, t1, t2, t3, bd);
                    Bf[np*2][0] = t0; Bf[np*2][1] = t1;
                    Bf[np*2+1][0] = t2; Bf[np*2+1][1] = t3;
                }
            }
#pragma unroll
            for (int mi = 0; mi < 4; mi++)
#pragma unroll
                for (int ni = 0; ni < 4; ni++)
                    MMA_TF32(acc[mi][ni], Af[mi], Bf[ni]);
        }
        __syncthreads();
        slot = slot == 2 ? 0 : slot + 1;
        nslot = nslot == 2 ? 0 : nslot + 1;
    }

    // ---------------- epilogue ----------------
    int sec = n0 >> 10;                       // uniform per CTA (ACT3)
    const float* bsel = (ACT == 3) ? (sec == 0 ? bias : (sec == 1 ? bias2 : bias3)) : bias;
    float* dst = (ACT == 3) ? (sec == 0 ? Cf : (sec == 1 ? Cf2 : Cf3)) : Cf;
    int nsub = (ACT == 3) ? (sec << 10) : 0;
    int rowstride = (ACT == 3) ? Ee : N;
#pragma unroll
    for (int mi = 0; mi < 4; mi++) {
#pragma unroll
        for (int half = 0; half < 2; half++) {
            int m = m0 + warpM * 64 + mi * 16 + (l >> 2) + half * 8;
#pragma unroll
            for (int ni = 0; ni < 4; ni++) {
                int n = n0 + warpN * 32 + ni * 8 + (l & 3) * 2;
                float v0 = acc[mi][ni][half * 2 + 0];
                float v1 = acc[mi][ni][half * 2 + 1];
                float2 bz = __ldg((const float2*)&bsel[n - nsub]);
                v0 += bz.x; v1 += bz.y;
                if (ACT == 1 || (ACT == 3 && sec < 2)) {
                    v0 = fmaxf(v0, 0.0f); v1 = fmaxf(v1, 0.0f);
                } else if (ACT == 2) {
                    v0 = 0.5f * v0 * (1.0f + erff(v0 * 0.70710678118654752f));
                    v1 = 0.5f * v1 * (1.0f + erff(v1 * 0.70710678118654752f));
                    v0 = to_tf32(v0); v1 = to_tf32(v1);   // feeds next GEMM A-operand
                }
                size_t off = (size_t)m * rowstride + (n - nsub);
                if (RES) {
                    float2 rv = *(const float2*)&res[off];
                    v0 += rv.x; v1 += rv.y;
                }
                *(float2*)&dst[off] = make_float2(v0, v1);
            }
        }
    }
}

// ===================== zero =====================
__global__ void zero_kernel(float* p, int n) {
    int i = blockIdx.x * blockDim.x + threadIdx.x;
    if (i < n) p[i] = 0.0f;
}

// ===================== kv reduction =====================
#define TSPLIT 4
__global__ __launch_bounds__(256) void kv_kernel(
    const float* __restrict__ Kp, const float* __restrict__ Vp,
    float* __restrict__ kv, float* __restrict__ ksum)
{
    int bh = blockIdx.x;
    int b = bh >> 4, h = bh & 15;
    int tid = threadIdx.x;
    __shared__ float ks_sh[32][64];
    __shared__ float vs_sh[32][64];
    __shared__ float s_sh[32], c_sh[32];

    int dd = tid & 63;
    int eb = tid >> 6;
    int e0 = eb * 16;
    float acc_s[16], acc_c[16];
#pragma unroll
    for (int i = 0; i < 16; i++) { acc_s[i] = 0.0f; acc_c[i] = 0.0f; }
    float ksum_s = 0.0f, ksum_c = 0.0f;

    int tbase = blockIdx.y * (Tt / TSPLIT);
    for (int tt = 0; tt < Tt / TSPLIT; tt += 32) {
        int t0 = tbase + tt;
#pragma unroll
        for (int ld = 0; ld < 2; ld++) {
            int id = tid + ld * 256;
            int r = id >> 4, c4 = (id & 15) * 4;
            size_t off = (size_t)(b * Tt + t0 + r) * Ee + h * 64 + c4;
            *(float4*)&ks_sh[r][c4] = *(const float4*)&Kp[off];
            *(float4*)&vs_sh[r][c4] = *(const float4*)&Vp[off];
        }
        if (tid < 32) {
            float idx = PIO2 * (float)(t0 + tid + 1) * (1.0f / Tt);
            s_sh[tid] = sinf(idx);
            c_sh[tid] = cosf(idx);
        }
        __syncthreads();
#pragma unroll 4
        for (int r = 0; r < 32; r++) {
            float kd = ks_sh[r][dd];
            float as = kd * s_sh[r];
            float ac = kd * c_sh[r];
            if (eb == 0) { ksum_s += as; ksum_c += ac; }
#pragma unroll
            for (int i = 0; i < 16; i++) {
                float ve = vs_sh[r][e0 + i];
                acc_s[i] = fmaf(as, ve, acc_s[i]);
                acc_c[i] = fmaf(ac, ve, acc_c[i]);
            }
        }
        __syncthreads();
    }
    float* kvb = kv + (size_t)bh * 128 * Dd;
#pragma unroll
    for (int i = 0; i < 16; i++) {
        atomicAdd(&kvb[dd * Dd + e0 + i], acc_s[i]);
        atomicAdd(&kvb[(64 + dd) * Dd + e0 + i], acc_c[i]);
    }
    if (eb == 0) {
        atomicAdd(&ksum[bh * 128 + dd], ksum_s);
        atomicAdd(&ksum[bh * 128 + 64 + dd], ksum_c);
    }
}

// ===================== attention: out -> tf32-rounded fp32 =================
__global__ __launch_bounds__(256) void attn_kernel(
    const float* __restrict__ Qp, const float* __restrict__ kv,
    const float* __restrict__ ksum, float* __restrict__ Op)
{
    int bh = blockIdx.y;
    int b = bh >> 4, h = bh & 15;
    int t0 = blockIdx.x * 32;
    int tid = threadIdx.x;

    __shared__ float kv_sh[128][64];
    __shared__ float q_sh[32][65];
    __shared__ float ksum_sh[128];
    __shared__ float den_sh[32], s_sh[32], c_sh[32];

#pragma unroll
    for (int ld = 0; ld < 8; ld++) {
        int id = tid + ld * 256;
        int r = id >> 4, c4 = (id & 15) * 4;
        *(float4*)&kv_sh[r][c4] = *(const float4*)&kv[((size_t)bh * 128 + r) * Dd + c4];
    }
#pragma unroll
    for (int ld = 0; ld < 2; ld++) {
        int id = tid + ld * 256;
        int r = id >> 4, c4 = (id & 15) * 4;
        float4 qv = *(const float4*)&Qp[(size_t)(b * Tt + t0 + r) * Ee + h * 64 + c4];
        q_sh[r][c4 + 0] = qv.x; q_sh[r][c4 + 1] = qv.y;
        q_sh[r][c4 + 2] = qv.z; q_sh[r][c4 + 3] = qv.w;
    }
    if (tid < 128) ksum_sh[tid] = ksum[bh * 128 + tid];
    if (tid < 32) {
        float idx = PIO2 * (float)(t0 + tid + 1) * (1.0f / Tt);
        s_sh[tid] = sinf(idx);
        c_sh[tid] = cosf(idx);
    }
    __syncthreads();

    if (tid < 32) {
        float ds = 0.0f, dc = 0.0f;
#pragma unroll 8
        for (int d = 0; d < 64; d++) {
            float qd = q_sh[tid][d];
            ds = fmaf(qd, ksum_sh[d], ds);
            dc = fmaf(qd, ksum_sh[64 + d], dc);
        }
        den_sh[tid] = s_sh[tid] * ds + c_sh[tid] * dc;
    }
    __syncthreads();

    int tl = tid & 31;
    int eb = tid >> 5;
    int e0 = eb * 8;
    float outs[8], outc[8];
#pragma unroll
    for (int j = 0; j < 8; j++) { outs[j] = 0.0f; outc[j] = 0.0f; }

#pragma unroll 4
    for (int d = 0; d < 64; d++) {
        float qd = q_sh[tl][d];
        float4 k0 = *(const float4*)&kv_sh[d][e0];
        float4 k1 = *(const float4*)&kv_sh[d][e0 + 4];
        float4 m0 = *(const float4*)&kv_sh[64 + d][e0];
        float4 m1 = *(const float4*)&kv_sh[64 + d][e0 + 4];
        outs[0]=fmaf(qd,k0.x,outs[0]); outs[1]=fmaf(qd,k0.y,outs[1]);
        outs[2]=fmaf(qd,k0.z,outs[2]); outs[3]=fmaf(qd,k0.w,outs[3]);
        outs[4]=fmaf(qd,k1.x,outs[4]); outs[5]=fmaf(qd,k1.y,outs[5]);
        outs[6]=fmaf(qd,k1.z,outs[6]); outs[7]=fmaf(qd,k1.w,outs[7]);
        outc[0]=fmaf(qd,m0.x,outc[0]); outc[1]=fmaf(qd,m0.y,outc[1]);
        outc[2]=fmaf(qd,m0.z,outc[2]); outc[3]=fmaf(qd,m0.w,outc[3]);
        outc[4]=fmaf(qd,m1.x,outc[4]); outc[5]=fmaf(qd,m1.y,outc[5]);
        outc[6]=fmaf(qd,m1.z,outc[6]); outc[7]=fmaf(qd,m1.w,outc[7]);
    }
    float z = 1.0f / fmaxf(den_sh[tl], 1e-6f);
    float s = s_sh[tl] * z, c = c_sh[tl] * z;
    float o[8];
#pragma unroll
    for (int j = 0; j < 8; j++) o[j] = to_tf32(s * outs[j] + c * outc[j]);
    size_t off = (size_t)(b * Tt + t0 + tl) * Ee + h * 64 + e0;
    *(float4*)&Op[off]     = make_float4(o[0], o[1], o[2], o[3]);
    *(float4*)&Op[off + 4] = make_float4(o[4], o[5], o[6], o[7]);
}

// ===================== launch =====================
extern "C" void kernel_launch(void* const* d_in, const int* in_sizes, int n_in,
                              void* d_out, int out_size) {
    const float* x      = (const float*)d_in[0];
    const float* ln1_w  = (const float*)d_in[1];
    const float* ln1_b  = (const float*)d_in[2];
    const float* wq     = (const float*)d_in[3];
    const float* bq     = (const float*)d_in[4];
    const float* wk     = (const float*)d_in[5];
    const float* bk     = (const float*)d_in[6];
    const float* wv     = (const float*)d_in[7];
    const float* bv     = (const float*)d_in[8];
    const float* wo     = (const float*)d_in[9];
    const float* bo     = (const float*)d_in[10];
    const float* ln2_w  = (const float*)d_in[11];
    const float* ln2_b  = (const float*)d_in[12];
    const float* w_fc   = (const float*)d_in[13];
    const float* b_fc   = (const float*)d_in[14];
    const float* w_proj = (const float*)d_in[15];
    const float* b_proj = (const float*)d_in[16];
    float* out = (float*)d_out;

    float *p_h, *p_attn, *p_fc, *p_q, *p_k, *p_v, *p_x2, *p_kv, *p_ksum;
    float *p_wqkv, *p_wo, *p_wfc, *p_wpj;
    cudaGetSymbolAddress((void**)&p_h,    g_h);
    cudaGetSymbolAddress((void**)&p_attn, g_attn);
    cudaGetSymbolAddress((void**)&p_fc,   g_fc);
    cudaGetSymbolAddress((void**)&p_q,    g_q);
    cudaGetSymbolAddress((void**)&p_k,    g_k);
    cudaGetSymbolAddress((void**)&p_v,    g_v);
    cudaGetSymbolAddress((void**)&p_x2,   g_x2);
    cudaGetSymbolAddress((void**)&p_kv,   g_kv);
    cudaGetSymbolAddress((void**)&p_ksum, g_ksum);
    cudaGetSymbolAddress((void**)&p_wqkv, g_wqkv);
    cudaGetSymbolAddress((void**)&p_wo,   g_wo);
    cudaGetSymbolAddress((void**)&p_wfc,  g_wfc);
    cudaGetSymbolAddress((void**)&p_wpj,  g_wpj);

    cudaFuncSetAttribute(gemm_tf32<3, false>, cudaFuncAttributeMaxDynamicSharedMemorySize, GT_SMEM);
    cudaFuncSetAttribute(gemm_tf32<0, true>,  cudaFuncAttributeMaxDynamicSharedMemorySize, GT_SMEM);
    cudaFuncSetAttribute(gemm_tf32<2, false>, cudaFuncAttributeMaxDynamicSharedMemorySize, GT_SMEM);

    // launch 0: h = LN1(x)
    ln_kernel<<<M_ROWS, 256>>>(x, ln1_w, ln1_b, p_h);
    // launch 1: QKV weight transpose (all 3 in one launch)
    transpose_qkv_kernel<<<dim3(Ee/32, Ee/32, 3), 256>>>(wq, wk, wv, p_wqkv);
    // launch 2: wo transpose
    transpose_tf32_kernel<<<dim3(Ee/32, Ee/32), 256>>>(wo, p_wo, Ee, Ee);
    // launch 3 (ncu capture target): fused QKV GEMM, N=3072
    dim3 gqkv(3*Ee / 128, M_ROWS / 128);
    gemm_tf32<3, false><<<gqkv, 256, GT_SMEM>>>(p_h, p_wqkv,
        bq, bk, bv, nullptr, p_q, p_k, p_v, M_ROWS, 3*Ee, Ee);

    // kv / ksum reduction
    zero_kernel<<<(Bb*Hh*128*Dd + 255) / 256, 256>>>(p_kv, Bb*Hh*128*Dd);
    zero_kernel<<<(Bb*Hh*128 + 255) / 256, 256>>>(p_ksum, Bb*Hh*128);
    kv_kernel<<<dim3(Bb * Hh, TSPLIT), 256>>>(p_k, p_v, p_kv, p_ksum);

    // attention output (tf32-rounded fp32)
    attn_kernel<<<dim3(Tt / 32, Bb * Hh), 256>>>(p_q, p_kv, p_ksum, p_attn);

    // x2 = x + attn @ wo + bo
    dim3 g1(Ee / 128, M_ROWS / 128);
    gemm_tf32<0, true><<<g1, 256, GT_SMEM>>>(p_attn, p_wo,
        bo, nullptr, nullptr, x, p_x2, nullptr, nullptr, M_ROWS, Ee, Ee);

    // h = LN2(x2)
    ln_kernel<<<M_ROWS, 256>>>(p_x2, ln2_w, ln2_b, p_h);

    // fc = gelu(h @ w_fc + b_fc)  (tf32-rounded)
    transpose_tf32_kernel<<<dim3(FF/32, Ee/32), 256>>>(w_fc, p_wfc, Ee, FF);
    dim3 g2(FF / 128, M_ROWS / 128);
    gemm_tf32<2, false><<<g2, 256, GT_SMEM>>>(p_h, p_wfc,
        b_fc, nullptr, nullptr, nullptr, p_fc, nullptr, nullptr, M_ROWS, FF, Ee);

    // out = x2 + fc @ w_proj + b_proj
    transpose_tf32_kernel<<<dim3(Ee/32, FF/32), 256>>>(w_proj, p_wpj, FF, Ee);
    gemm_tf32<0, true><<<g1, 256, GT_SMEM>>>(p_fc, p_wpj,
        b_proj, nullptr, nullptr, p_x2, out, nullptr, nullptr, M_ROWS, Ee, FF);
}

// round 8
// speedup vs baseline: 4.2759x; 1.0961x over previous
#include <cuda_runtime.h>
#include <cuda_bf16.h>
#include <math.h>
#include <stdint.h>

#define Bb 4
#define Tt 4096
#define Ee 1024
#define Hh 16
#define Dd 64
#define M_ROWS (Bb*Tt)          // 16384
#define FF (4*Ee)               // 4096
#define PIO2 1.5707963267948966f

// ===================== PTX helpers (baseline ISA only) =====================
__device__ __forceinline__ uint32_t smem_to_u32(const void* p) {
    uint32_t a;
    asm("{ .reg .u64 t; cvta.to.shared.u64 t, %1; cvt.u32.u64 %0, t; }" : "=r"(a) : "l"(p));
    return a;
}
#define CP_ASYNC16(saddr, gptr) \
    asm volatile("cp.async.cg.shared.global [%0], [%1], 16;" :: "r"(saddr), "l"(gptr))
#define CP_COMMIT() asm volatile("cp.async.commit_group;" ::: "memory")
#define CP_WAIT1()  asm volatile("cp.async.wait_group 1;" ::: "memory")

#define LDSM_X4(r0,r1,r2,r3, addr) \
    asm volatile("ldmatrix.sync.aligned.m8n8.x4.shared.b16 {%0,%1,%2,%3}, [%4];" \
        : "=r"(r0),"=r"(r1),"=r"(r2),"=r"(r3) : "r"(addr))

#define MMA_TF32(d, a, b) \
    asm volatile("mma.sync.aligned.m16n8k8.row.col.f32.tf32.tf32.f32 " \
        "{%0,%1,%2,%3}, {%4,%5,%6,%7}, {%8,%9}, {%0,%1,%2,%3};" \
        : "+f"((d)[0]),"+f"((d)[1]),"+f"((d)[2]),"+f"((d)[3]) \
        : "r"((a)[0]),"r"((a)[1]),"r"((a)[2]),"r"((a)[3]), "r"((b)[0]),"r"((b)[1]))

__device__ __forceinline__ float to_tf32(float x) {
    float r;
    asm("cvt.rna.tf32.f32 %0, %1;" : "=f"(r) : "f"(x));
    return r;
}

// ===================== scratch (device globals) =====================
__device__ float g_h   [M_ROWS*Ee];           // LN out (tf32-rounded fp32)
__device__ float g_attn[M_ROWS*Ee];           // attn out (tf32-rounded)
__device__ float g_fc  [(size_t)M_ROWS*FF];   // gelu out (tf32-rounded)
__device__ float g_q [M_ROWS*Ee];
__device__ float g_k [M_ROWS*Ee];
__device__ float g_v [M_ROWS*Ee];
__device__ float g_x2[M_ROWS*Ee];
__device__ float g_kv  [Bb*Hh*128*Dd];
__device__ float g_ksum[Bb*Hh*128];
// transposed tf32-rounded weights: [N, K] fp32
__device__ float g_wqkv[3*Ee*Ee];             // q|k|v stacked in N
__device__ float g_wo  [Ee*Ee];
__device__ float g_wfc [(size_t)FF*Ee];
__device__ float g_wpj [(size_t)Ee*FF];

// ===================== transpose + tf32-round: W[K,N] -> T[N,K] ============
__global__ void transpose_tf32_kernel(const float* __restrict__ W,
                                      float* __restrict__ T, int K, int N) {
    __shared__ float ts[32][33];
    int n0 = blockIdx.x * 32, k0 = blockIdx.y * 32;
    int tx = threadIdx.x & 31, ty = threadIdx.x >> 5;
#pragma unroll
    for (int i = 0; i < 32; i += 8)
        ts[ty + i][tx] = W[(size_t)(k0 + ty + i) * N + n0 + tx];
    __syncthreads();
#pragma unroll
    for (int i = 0; i < 32; i += 8)
        T[(size_t)(n0 + ty + i) * K + k0 + tx] = to_tf32(ts[tx][ty + i]);
}

// all three QKV weights in one launch (blockIdx.z selects)
__global__ void transpose_qkv_kernel(const float* __restrict__ wq,
                                     const float* __restrict__ wk,
                                     const float* __restrict__ wv,
                                     float* __restrict__ T) {
    __shared__ float ts[32][33];
    const float* W = blockIdx.z == 0 ? wq : (blockIdx.z == 1 ? wk : wv);
    float* Tz = T + (size_t)blockIdx.z * Ee * Ee;
    int n0 = blockIdx.x * 32, k0 = blockIdx.y * 32;
    int tx = threadIdx.x & 31, ty = threadIdx.x >> 5;
#pragma unroll
    for (int i = 0; i < 32; i += 8)
        ts[ty + i][tx] = W[(size_t)(k0 + ty + i) * Ee + n0 + tx];
    __syncthreads();
#pragma unroll
    for (int i = 0; i < 32; i += 8)
        Tz[(size_t)(n0 + ty + i) * Ee + k0 + tx] = to_tf32(ts[tx][ty + i]);
}

// ===================== LayerNorm -> tf32-rounded fp32 =====================
__global__ void ln_kernel(const float* __restrict__ X, const float* __restrict__ w,
                          const float* __restrict__ b, float* __restrict__ Y) {
    int row = blockIdx.x;
    int tid = threadIdx.x;                 // 256 threads
    const float4* x4 = (const float4*)(X + (size_t)row * Ee);
    float4 v = x4[tid];
    __shared__ float red[8];

    float s = v.x + v.y + v.z + v.w;
    for (int o = 16; o > 0; o >>= 1) s += __shfl_down_sync(0xffffffffu, s, o);
    if ((tid & 31) == 0) red[tid >> 5] = s;
    __syncthreads();
    if (tid < 8) {
        float t = red[tid];
        for (int o = 4; o > 0; o >>= 1) t += __shfl_down_sync(0xffu, t, o);
        if (tid == 0) red[0] = t;
    }
    __syncthreads();
    float mu = red[0] * (1.0f / Ee);
    __syncthreads();

    float dx = v.x - mu, dy = v.y - mu, dz = v.z - mu, dw = v.w - mu;
    float ss = dx*dx + dy*dy + dz*dz + dw*dw;
    for (int o = 16; o > 0; o >>= 1) ss += __shfl_down_sync(0xffffffffu, ss, o);
    if ((tid & 31) == 0) red[tid >> 5] = ss;
    __syncthreads();
    if (tid < 8) {
        float t = red[tid];
        for (int o = 4; o > 0; o >>= 1) t += __shfl_down_sync(0xffu, t, o);
        if (tid == 0) red[0] = t;
    }
    __syncthreads();
    float rstd = rsqrtf(red[0] * (1.0f / Ee) + 1e-5f);

    float4 wv = ((const float4*)w)[tid];
    float4 bv = ((const float4*)b)[tid];
    float4 o;
    o.x = to_tf32(dx * rstd * wv.x + bv.x);
    o.y = to_tf32(dy * rstd * wv.y + bv.y);
    o.z = to_tf32(dz * rstd * wv.z + bv.z);
    o.w = to_tf32(dw * rstd * wv.w + bv.w);
    ((float4*)(Y + (size_t)row * Ee))[tid] = o;
}

// ===================== tf32 mma.sync GEMM ==================================
// C[m,n] = act( A[m,:] @ Bt[n,:]^T + bias[n] ) (+ res)
// Tile 128x128, K-chunk 32, 3-stage cp.async pipeline, 8 warps, 2 CTAs/SM.
// ACT: 0 none, 1 relu, 2 gelu(+tf32 out), 3 fused-QKV.
#define STAGE_BYTES 32768        // A 16KB + B 16KB (K-chunk 32 x fp32)
#define GT_SMEM (3*STAGE_BYTES)  // 96KB -> 2 CTAs/SM

__device__ __forceinline__ void load_stage(
    uint32_t sbase, int slot, int tid, int m0, int n0, int k0, int K,
    const float* A, const float* B)
{
    uint32_t sb = sbase + slot * STAGE_BYTES;
#pragma unroll
    for (int i = 0; i < 4; i++) {
        int u = tid + i * 256;        // 0..1023 16B-chunks (128 rows x 8 chunks)
        int r = u >> 3, c = u & 7;
        uint32_t phys = (uint32_t)(c ^ (r & 7));
        CP_ASYNC16(sb + r * 128 + phys * 16, A + (size_t)(m0 + r) * K + k0 + c * 4);
    }
#pragma unroll
    for (int i = 0; i < 4; i++) {
        int u = tid + i * 256;
        int r = u >> 3, c = u & 7;
        uint32_t phys = (uint32_t)(c ^ (r & 7));
        CP_ASYNC16(sb + 16384 + r * 128 + phys * 16, B + (size_t)(n0 + r) * K + k0 + c * 4);
    }
}

template<int ACT, bool RES>
__global__ __launch_bounds__(256, 2) void gemm_tf32(
    const float* __restrict__ A, const float* __restrict__ Bt,
    const float* __restrict__ bias, const float* __restrict__ bias2,
    const float* __restrict__ bias3, const float* __restrict__ res,
    float* __restrict__ Cf, float* __restrict__ Cf2, float* __restrict__ Cf3,
    int M, int N, int K)
{
    extern __shared__ char smem[];
    uint32_t sbase = smem_to_u32(smem);
    int tid = threadIdx.x;
    int wid = tid >> 5, l = tid & 31;
    int warpM = wid >> 2, warpN = wid & 3;     // 2 x 4 warps, warp tile 64x32
    int m0 = blockIdx.y * 128, n0 = blockIdx.x * 128;

    // lane addressing for ldmatrix (b16-view of tf32 tiles; 128B rows, 8 chunks)
    int xr = l & 7;                                   // swizzle xor
    int rowlaneA = (l & 7) + ((l >> 3) & 1) * 8;      // 0..15 within m16
    int chA = (l >> 4) & 1;
    int rowlaneB = ((l >> 4) & 1) * 8 + (l & 7);
    int chB = (l >> 3) & 1;

    float acc[4][4][4];
#pragma unroll
    for (int mi = 0; mi < 4; mi++)
#pragma unroll
        for (int ni = 0; ni < 4; ni++)
#pragma unroll
            for (int j = 0; j < 4; j++) acc[mi][ni][j] = 0.0f;

    const int NC = K >> 5;                 // K-chunk 32
    load_stage(sbase, 0, tid, m0, n0, 0, K, A, Bt);
    CP_COMMIT();
    load_stage(sbase, 1, tid, m0, n0, 32, K, A, Bt);
    CP_COMMIT();

    int slot = 0, nslot = 2;
    for (int c = 0; c < NC; c++) {
        CP_WAIT1();
        __syncthreads();
        if (c + 2 < NC)
            load_stage(sbase, nslot, tid, m0, n0, (c + 2) * 32, K, A, Bt);
        CP_COMMIT();
        uint32_t sA = sbase + slot * STAGE_BYTES;
        uint32_t sB = sA + 16384;
#pragma unroll
        for (int k8 = 0; k8 < 4; k8++) {
            uint32_t Af[4][4], Bf[4][2];
            {
                int cl = 2 * k8 + chA;
                uint32_t phys = (uint32_t)(cl ^ xr);
#pragma unroll
                for (int mi = 0; mi < 4; mi++) {
                    uint32_t ad = sA + (uint32_t)((warpM * 64 + mi * 16 + rowlaneA) * 128) + phys * 16;
                    LDSM_X4(Af[mi][0], Af[mi][1], Af[mi][2], Af[mi][3], ad);
                }
            }
            {
                int cl = 2 * k8 + chB;
                uint32_t phys = (uint32_t)(cl ^ xr);
#pragma unroll
                for (int np = 0; np < 2; np++) {
                    uint32_t bd = sB + (uint32_t)((warpN * 32 + np * 16 + rowlaneB) * 128) + phys * 16;
                    uint32_t t0, t1, t2, t3;
                    LDSM_X4(t0, t1, t2, t3, bd);
                    Bf[np*2][0] = t0; Bf[np*2][1] = t1;
                    Bf[np*2+1][0] = t2; Bf[np*2+1][1] = t3;
                }
            }
#pragma unroll
            for (int mi = 0; mi < 4; mi++)
#pragma unroll
                for (int ni = 0; ni < 4; ni++)
                    MMA_TF32(acc[mi][ni], Af[mi], Bf[ni]);
        }
        __syncthreads();
        slot = slot == 2 ? 0 : slot + 1;
        nslot = nslot == 2 ? 0 : nslot + 1;
    }

    // ---------------- epilogue ----------------
    int sec = n0 >> 10;                       // uniform per CTA (ACT3)
    const float* bsel = (ACT == 3) ? (sec == 0 ? bias : (sec == 1 ? bias2 : bias3)) : bias;
    float* dst = (ACT == 3) ? (sec == 0 ? Cf : (sec == 1 ? Cf2 : Cf3)) : Cf;
    int nsub = (ACT == 3) ? (sec << 10) : 0;
    int rowstride = (ACT == 3) ? Ee : N;
#pragma unroll
    for (int mi = 0; mi < 4; mi++) {
#pragma unroll
        for (int half = 0; half < 2; half++) {
            int m = m0 + warpM * 64 + mi * 16 + (l >> 2) + half * 8;
#pragma unroll
            for (int ni = 0; ni < 4; ni++) {
                int n = n0 + warpN * 32 + ni * 8 + (l & 3) * 2;
                float v0 = acc[mi][ni][half * 2 + 0];
                float v1 = acc[mi][ni][half * 2 + 1];
                float2 bz = __ldg((const float2*)&bsel[n - nsub]);
                v0 += bz.x; v1 += bz.y;
                if (ACT == 1 || (ACT == 3 && sec < 2)) {
                    v0 = fmaxf(v0, 0.0f); v1 = fmaxf(v1, 0.0f);
                } else if (ACT == 2) {
                    v0 = 0.5f * v0 * (1.0f + erff(v0 * 0.70710678118654752f));
                    v1 = 0.5f * v1 * (1.0f + erff(v1 * 0.70710678118654752f));
                    v0 = to_tf32(v0); v1 = to_tf32(v1);   // feeds next GEMM A-operand
                }
                size_t off = (size_t)m * rowstride + (n - nsub);
                if (RES) {
                    float2 rv = *(const float2*)&res[off];
                    v0 += rv.x; v1 += rv.y;
                }
                *(float2*)&dst[off] = make_float2(v0, v1);
            }
        }
    }
}

// ===================== zero =====================
__global__ void zero_kernel(float* p, int n) {
    int i = blockIdx.x * blockDim.x + threadIdx.x;
    if (i < n) p[i] = 0.0f;
}

// ===================== kv reduction =====================
#define TSPLIT 4
__global__ __launch_bounds__(256) void kv_kernel(
    const float* __restrict__ Kp, const float* __restrict__ Vp,
    float* __restrict__ kv, float* __restrict__ ksum)
{
    int bh = blockIdx.x;
    int b = bh >> 4, h = bh & 15;
    int tid = threadIdx.x;
    __shared__ float ks_sh[32][64];
    __shared__ float vs_sh[32][64];
    __shared__ float s_sh[32], c_sh[32];

    int dd = tid & 63;
    int eb = tid >> 6;
    int e0 = eb * 16;
    float acc_s[16], acc_c[16];
#pragma unroll
    for (int i = 0; i < 16; i++) { acc_s[i] = 0.0f; acc_c[i] = 0.0f; }
    float ksum_s = 0.0f, ksum_c = 0.0f;

    int tbase = blockIdx.y * (Tt / TSPLIT);
    for (int tt = 0; tt < Tt / TSPLIT; tt += 32) {
        int t0 = tbase + tt;
#pragma unroll
        for (int ld = 0; ld < 2; ld++) {
            int id = tid + ld * 256;
            int r = id >> 4, c4 = (id & 15) * 4;
            size_t off = (size_t)(b * Tt + t0 + r) * Ee + h * 64 + c4;
            *(float4*)&ks_sh[r][c4] = *(const float4*)&Kp[off];
            *(float4*)&vs_sh[r][c4] = *(const float4*)&Vp[off];
        }
        if (tid < 32) {
            float idx = PIO2 * (float)(t0 + tid + 1) * (1.0f / Tt);
            s_sh[tid] = sinf(idx);
            c_sh[tid] = cosf(idx);
        }
        __syncthreads();
#pragma unroll 4
        for (int r = 0; r < 32; r++) {
            float kd = ks_sh[r][dd];
            float as = kd * s_sh[r];
            float ac = kd * c_sh[r];
            if (eb == 0) { ksum_s += as; ksum_c += ac; }
#pragma unroll
            for (int i = 0; i < 16; i++) {
                float ve = vs_sh[r][e0 + i];
                acc_s[i] = fmaf(as, ve, acc_s[i]);
                acc_c[i] = fmaf(ac, ve, acc_c[i]);
            }
        }
        __syncthreads();
    }
    float* kvb = kv + (size_t)bh * 128 * Dd;
#pragma unroll
    for (int i = 0; i < 16; i++) {
        atomicAdd(&kvb[dd * Dd + e0 + i], acc_s[i]);
        atomicAdd(&kvb[(64 + dd) * Dd + e0 + i], acc_c[i]);
    }
    if (eb == 0) {
        atomicAdd(&ksum[bh * 128 + dd], ksum_s);
        atomicAdd(&ksum[bh * 128 + 64 + dd], ksum_c);
    }
}

// ===================== attention: out -> tf32-rounded fp32 =================
__global__ __launch_bounds__(256) void attn_kernel(
    const float* __restrict__ Qp, const float* __restrict__ kv,
    const float* __restrict__ ksum, float* __restrict__ Op)
{
    int bh = blockIdx.y;
    int b = bh >> 4, h = bh & 15;
    int t0 = blockIdx.x * 32;
    int tid = threadIdx.x;

    __shared__ float kv_sh[128][64];
    __shared__ float q_sh[32][65];
    __shared__ float ksum_sh[128];
    __shared__ float den_sh[32], s_sh[32], c_sh[32];

#pragma unroll
    for (int ld = 0; ld < 8; ld++) {
        int id = tid + ld * 256;
        int r = id >> 4, c4 = (id & 15) * 4;
        *(float4*)&kv_sh[r][c4] = *(const float4*)&kv[((size_t)bh * 128 + r) * Dd + c4];
    }
#pragma unroll
    for (int ld = 0; ld < 2; ld++) {
        int id = tid + ld * 256;
        int r = id >> 4, c4 = (id & 15) * 4;
        float4 qv = *(const float4*)&Qp[(size_t)(b * Tt + t0 + r) * Ee + h * 64 + c4];
        q_sh[r][c4 + 0] = qv.x; q_sh[r][c4 + 1] = qv.y;
        q_sh[r][c4 + 2] = qv.z; q_sh[r][c4 + 3] = qv.w;
    }
    if (tid < 128) ksum_sh[tid] = ksum[bh * 128 + tid];
    if (tid < 32) {
        float idx = PIO2 * (float)(t0 + tid + 1) * (1.0f / Tt);
        s_sh[tid] = sinf(idx);
        c_sh[tid] = cosf(idx);
    }
    __syncthreads();

    if (tid < 32) {
        float ds = 0.0f, dc = 0.0f;
#pragma unroll 8
        for (int d = 0; d < 64; d++) {
            float qd = q_sh[tid][d];
            ds = fmaf(qd, ksum_sh[d], ds);
            dc = fmaf(qd, ksum_sh[64 + d], dc);
        }
        den_sh[tid] = s_sh[tid] * ds + c_sh[tid] * dc;
    }
    __syncthreads();

    int tl = tid & 31;
    int eb = tid >> 5;
    int e0 = eb * 8;
    float outs[8], outc[8];
#pragma unroll
    for (int j = 0; j < 8; j++) { outs[j] = 0.0f; outc[j] = 0.0f; }

#pragma unroll 4
    for (int d = 0; d < 64; d++) {
        float qd = q_sh[tl][d];
        float4 k0 = *(const float4*)&kv_sh[d][e0];
        float4 k1 = *(const float4*)&kv_sh[d][e0 + 4];
        float4 m0 = *(const float4*)&kv_sh[64 + d][e0];
        float4 m1 = *(const float4*)&kv_sh[64 + d][e0 + 4];
        outs[0]=fmaf(qd,k0.x,outs[0]); outs[1]=fmaf(qd,k0.y,outs[1]);
        outs[2]=fmaf(qd,k0.z,outs[2]); outs[3]=fmaf(qd,k0.w,outs[3]);
        outs[4]=fmaf(qd,k1.x,outs[4]); outs[5]=fmaf(qd,k1.y,outs[5]);
        outs[6]=fmaf(qd,k1.z,outs[6]); outs[7]=fmaf(qd,k1.w,outs[7]);
        outc[0]=fmaf(qd,m0.x,outc[0]); outc[1]=fmaf(qd,m0.y,outc[1]);
        outc[2]=fmaf(qd,m0.z,outc[2]); outc[3]=fmaf(qd,m0.w,outc[3]);
        outc[4]=fmaf(qd,m1.x,outc[4]); outc[5]=fmaf(qd,m1.y,outc[5]);
        outc[6]=fmaf(qd,m1.z,outc[6]); outc[7]=fmaf(qd,m1.w,outc[7]);
    }
    float z = 1.0f / fmaxf(den_sh[tl], 1e-6f);
    float s = s_sh[tl] * z, c = c_sh[tl] * z;
    float o[8];
#pragma unroll
    for (int j = 0; j < 8; j++) o[j] = to_tf32(s * outs[j] + c * outc[j]);
    size_t off = (size_t)(b * Tt + t0 + tl) * Ee + h * 64 + e0;
    *(float4*)&Op[off]     = make_float4(o[0], o[1], o[2], o[3]);
    *(float4*)&Op[off + 4] = make_float4(o[4], o[5], o[6], o[7]);
}

// ===================== launch =====================
extern "C" void kernel_launch(void* const* d_in, const int* in_sizes, int n_in,
                              void* d_out, int out_size) {
    const float* x      = (const float*)d_in[0];
    const float* ln1_w  = (const float*)d_in[1];
    const float* ln1_b  = (const float*)d_in[2];
    const float* wq     = (const float*)d_in[3];
    const float* bq     = (const float*)d_in[4];
    const float* wk     = (const float*)d_in[5];
    const float* bk     = (const float*)d_in[6];
    const float* wv     = (const float*)d_in[7];
    const float* bv     = (const float*)d_in[8];
    const float* wo     = (const float*)d_in[9];
    const float* bo     = (const float*)d_in[10];
    const float* ln2_w  = (const float*)d_in[11];
    const float* ln2_b  = (const float*)d_in[12];
    const float* w_fc   = (const float*)d_in[13];
    const float* b_fc   = (const float*)d_in[14];
    const float* w_proj = (const float*)d_in[15];
    const float* b_proj = (const float*)d_in[16];
    float* out = (float*)d_out;

    float *p_h, *p_attn, *p_fc, *p_q, *p_k, *p_v, *p_x2, *p_kv, *p_ksum;
    float *p_wqkv, *p_wo, *p_wfc, *p_wpj;
    cudaGetSymbolAddress((void**)&p_h,    g_h);
    cudaGetSymbolAddress((void**)&p_attn, g_attn);
    cudaGetSymbolAddress((void**)&p_fc,   g_fc);
    cudaGetSymbolAddress((void**)&p_q,    g_q);
    cudaGetSymbolAddress((void**)&p_k,    g_k);
    cudaGetSymbolAddress((void**)&p_v,    g_v);
    cudaGetSymbolAddress((void**)&p_x2,   g_x2);
    cudaGetSymbolAddress((void**)&p_kv,   g_kv);
    cudaGetSymbolAddress((void**)&p_ksum, g_ksum);
    cudaGetSymbolAddress((void**)&p_wqkv, g_wqkv);
    cudaGetSymbolAddress((void**)&p_wo,   g_wo);
    cudaGetSymbolAddress((void**)&p_wfc,  g_wfc);
    cudaGetSymbolAddress((void**)&p_wpj,  g_wpj);

    cudaFuncSetAttribute(gemm_tf32<3, false>, cudaFuncAttributeMaxDynamicSharedMemorySize, GT_SMEM);
    cudaFuncSetAttribute(gemm_tf32<0, true>,  cudaFuncAttributeMaxDynamicSharedMemorySize, GT_SMEM);
    cudaFuncSetAttribute(gemm_tf32<2, false>, cudaFuncAttributeMaxDynamicSharedMemorySize, GT_SMEM);

    // launch 0: h = LN1(x)
    ln_kernel<<<M_ROWS, 256>>>(x, ln1_w, ln1_b, p_h);
    // launch 1: QKV weight transpose (all 3 in one launch)
    transpose_qkv_kernel<<<dim3(Ee/32, Ee/32, 3), 256>>>(wq, wk, wv, p_wqkv);
    // launch 2: wo transpose
    transpose_tf32_kernel<<<dim3(Ee/32, Ee/32), 256>>>(wo, p_wo, Ee, Ee);
    // launch 3 (ncu capture target): fused QKV GEMM, N=3072
    dim3 gqkv(3*Ee / 128, M_ROWS / 128);
    gemm_tf32<3, false><<<gqkv, 256, GT_SMEM>>>(p_h, p_wqkv,
        bq, bk, bv, nullptr, p_q, p_k, p_v, M_ROWS, 3*Ee, Ee);

    // kv / ksum reduction
    zero_kernel<<<(Bb*Hh*128*Dd + 255) / 256, 256>>>(p_kv, Bb*Hh*128*Dd);
    zero_kernel<<<(Bb*Hh*128 + 255) / 256, 256>>>(p_ksum, Bb*Hh*128);
    kv_kernel<<<dim3(Bb * Hh, TSPLIT), 256>>>(p_k, p_v, p_kv, p_ksum);

    // attention output (tf32-rounded fp32)
    attn_kernel<<<dim3(Tt / 32, Bb * Hh), 256>>>(p_q, p_kv, p_ksum, p_attn);

    // x2 = x + attn @ wo + bo
    dim3 g1(Ee / 128, M_ROWS / 128);
    gemm_tf32<0, true><<<g1, 256, GT_SMEM>>>(p_attn, p_wo,
        bo, nullptr, nullptr, x, p_x2, nullptr, nullptr, M_ROWS, Ee, Ee);

    // h = LN2(x2)
    ln_kernel<<<M_ROWS, 256>>>(p_x2, ln2_w, ln2_b, p_h);

    // fc = gelu(h @ w_fc + b_fc)  (tf32-rounded)
    transpose_tf32_kernel<<<dim3(FF/32, Ee/32), 256>>>(w_fc, p_wfc, Ee, FF);
    dim3 g2(FF / 128, M_ROWS / 128);
    gemm_tf32<2, false><<<g2, 256, GT_SMEM>>>(p_h, p_wfc,
        b_fc, nullptr, nullptr, nullptr, p_fc, nullptr, nullptr, M_ROWS, FF, Ee);

    // out = x2 + fc @ w_proj + b_proj
    transpose_tf32_kernel<<<dim3(Ee/32, FF/32), 256>>>(w_proj, p_wpj, FF, Ee);
    gemm_tf32<0, true><<<g1, 256, GT_SMEM>>>(p_fc, p_wpj,
        b_proj, nullptr, nullptr, p_x2, out, nullptr, nullptr, M_ROWS, Ee, FF);
}

// round 9
// speedup vs baseline: 4.3062x; 1.0071x over previous
#include <cuda_runtime.h>
#include <cuda_bf16.h>
#include <math.h>
#include <stdint.h>

#define Bb 4
#define Tt 4096
#define Ee 1024
#define Hh 16
#define Dd 64
#define M_ROWS (Bb*Tt)          // 16384
#define FF (4*Ee)               // 4096
#define PIO2 1.5707963267948966f

// ===================== PTX helpers (baseline ISA only) =====================
__device__ __forceinline__ uint32_t smem_to_u32(const void* p) {
    uint32_t a;
    asm("{ .reg .u64 t; cvta.to.shared.u64 t, %1; cvt.u32.u64 %0, t; }" : "=r"(a) : "l"(p));
    return a;
}
#define CP_ASYNC16(saddr, gptr) \
    asm volatile("cp.async.cg.shared.global [%0], [%1], 16;" :: "r"(saddr), "l"(gptr))
#define CP_COMMIT() asm volatile("cp.async.commit_group;" ::: "memory")
#define CP_WAIT1()  asm volatile("cp.async.wait_group 1;" ::: "memory")

#define LDSM_X4(r0,r1,r2,r3, addr) \
    asm volatile("ldmatrix.sync.aligned.m8n8.x4.shared.b16 {%0,%1,%2,%3}, [%4];" \
        : "=r"(r0),"=r"(r1),"=r"(r2),"=r"(r3) : "r"(addr))

#define MMA_TF32(d, a, b) \
    asm volatile("mma.sync.aligned.m16n8k8.row.col.f32.tf32.tf32.f32 " \
        "{%0,%1,%2,%3}, {%4,%5,%6,%7}, {%8,%9}, {%0,%1,%2,%3};" \
        : "+f"((d)[0]),"+f"((d)[1]),"+f"((d)[2]),"+f"((d)[3]) \
        : "r"((a)[0]),"r"((a)[1]),"r"((a)[2]),"r"((a)[3]), "r"((b)[0]),"r"((b)[1]))

__device__ __forceinline__ float to_tf32(float x) {
    float r;
    asm("cvt.rna.tf32.f32 %0, %1;" : "=f"(r) : "f"(x));
    return r;
}

// ===================== scratch (device globals) =====================
__device__ float g_h   [M_ROWS*Ee];           // LN out (tf32-rounded fp32)
__device__ float g_attn[M_ROWS*Ee];           // attn out (tf32-rounded)
__device__ float g_fc  [(size_t)M_ROWS*FF];   // gelu out (tf32-rounded)
__device__ float g_q [M_ROWS*Ee];
__device__ float g_k [M_ROWS*Ee];
__device__ float g_v [M_ROWS*Ee];
__device__ float g_x2[M_ROWS*Ee];
__device__ float g_kv  [Bb*Hh*128*Dd];
__device__ float g_ksum[Bb*Hh*128];
// transposed tf32-rounded weights: [N, K] fp32
__device__ float g_wqkv[3*Ee*Ee];             // q|k|v stacked in N
__device__ float g_wo  [Ee*Ee];
__device__ float g_wfc [(size_t)FF*Ee];
__device__ float g_wpj [(size_t)Ee*FF];

// ===================== transpose + tf32-round: W[K,N] -> T[N,K] ============
__global__ void transpose_tf32_kernel(const float* __restrict__ W,
                                      float* __restrict__ T, int K, int N) {
    __shared__ float ts[32][33];
    int n0 = blockIdx.x * 32, k0 = blockIdx.y * 32;
    int tx = threadIdx.x & 31, ty = threadIdx.x >> 5;
#pragma unroll
    for (int i = 0; i < 32; i += 8)
        ts[ty + i][tx] = W[(size_t)(k0 + ty + i) * N + n0 + tx];
    __syncthreads();
#pragma unroll
    for (int i = 0; i < 32; i += 8)
        T[(size_t)(n0 + ty + i) * K + k0 + tx] = to_tf32(ts[tx][ty + i]);
}

// all three QKV weights in one launch (blockIdx.z selects)
__global__ void transpose_qkv_kernel(const float* __restrict__ wq,
                                     const float* __restrict__ wk,
                                     const float* __restrict__ wv,
                                     float* __restrict__ T) {
    __shared__ float ts[32][33];
    const float* W = blockIdx.z == 0 ? wq : (blockIdx.z == 1 ? wk : wv);
    float* Tz = T + (size_t)blockIdx.z * Ee * Ee;
    int n0 = blockIdx.x * 32, k0 = blockIdx.y * 32;
    int tx = threadIdx.x & 31, ty = threadIdx.x >> 5;
#pragma unroll
    for (int i = 0; i < 32; i += 8)
        ts[ty + i][tx] = W[(size_t)(k0 + ty + i) * Ee + n0 + tx];
    __syncthreads();
#pragma unroll
    for (int i = 0; i < 32; i += 8)
        Tz[(size_t)(n0 + ty + i) * Ee + k0 + tx] = to_tf32(ts[tx][ty + i]);
}

// ===================== LayerNorm -> tf32-rounded fp32 =====================
__global__ void ln_kernel(const float* __restrict__ X, const float* __restrict__ w,
                          const float* __restrict__ b, float* __restrict__ Y) {
    int row = blockIdx.x;
    int tid = threadIdx.x;                 // 256 threads
    const float4* x4 = (const float4*)(X + (size_t)row * Ee);
    float4 v = x4[tid];
    __shared__ float red[8];

    float s = v.x + v.y + v.z + v.w;
    for (int o = 16; o > 0; o >>= 1) s += __shfl_down_sync(0xffffffffu, s, o);
    if ((tid & 31) == 0) red[tid >> 5] = s;
    __syncthreads();
    if (tid < 8) {
        float t = red[tid];
        for (int o = 4; o > 0; o >>= 1) t += __shfl_down_sync(0xffu, t, o);
        if (tid == 0) red[0] = t;
    }
    __syncthreads();
    float mu = red[0] * (1.0f / Ee);
    __syncthreads();

    float dx = v.x - mu, dy = v.y - mu, dz = v.z - mu, dw = v.w - mu;
    float ss = dx*dx + dy*dy + dz*dz + dw*dw;
    for (int o = 16; o > 0; o >>= 1) ss += __shfl_down_sync(0xffffffffu, ss, o);
    if ((tid & 31) == 0) red[tid >> 5] = ss;
    __syncthreads();
    if (tid < 8) {
        float t = red[tid];
        for (int o = 4; o > 0; o >>= 1) t += __shfl_down_sync(0xffu, t, o);
        if (tid == 0) red[0] = t;
    }
    __syncthreads();
    float rstd = rsqrtf(red[0] * (1.0f / Ee) + 1e-5f);

    float4 wv = ((const float4*)w)[tid];
    float4 bv = ((const float4*)b)[tid];
    float4 o;
    o.x = to_tf32(dx * rstd * wv.x + bv.x);
    o.y = to_tf32(dy * rstd * wv.y + bv.y);
    o.z = to_tf32(dz * rstd * wv.z + bv.z);
    o.w = to_tf32(dw * rstd * wv.w + bv.w);
    ((float4*)(Y + (size_t)row * Ee))[tid] = o;
}

// ===================== tf32 mma.sync GEMM ==================================
// C[m,n] = act( A[m,:] @ Bt[n,:]^T + bias[n] ) (+ res)
// Tile 128x128, K-chunk 32, 3-stage cp.async pipeline, 8 warps, 2 CTAs/SM.
// ONE barrier per chunk (post-compute barrier proven redundant: compute(c)
// precedes syncA(c+1) in program order, which guards slot(c) overwrites).
// ACT: 0 none, 1 relu, 2 gelu(+tf32 out), 3 fused-QKV.
#define STAGE_BYTES 32768        // A 16KB + B 16KB (K-chunk 32 x fp32)
#define GT_SMEM (3*STAGE_BYTES)  // 96KB -> 2 CTAs/SM

__device__ __forceinline__ void load_stage(
    uint32_t sbase, int slot, int tid, int m0, int n0, int k0, int K,
    const float* A, const float* B)
{
    uint32_t sb = sbase + slot * STAGE_BYTES;
#pragma unroll
    for (int i = 0; i < 4; i++) {
        int u = tid + i * 256;        // 0..1023 16B-chunks (128 rows x 8 chunks)
        int r = u >> 3, c = u & 7;
        uint32_t phys = (uint32_t)(c ^ (r & 7));
        CP_ASYNC16(sb + r * 128 + phys * 16, A + (size_t)(m0 + r) * K + k0 + c * 4);
    }
#pragma unroll
    for (int i = 0; i < 4; i++) {
        int u = tid + i * 256;
        int r = u >> 3, c = u & 7;
        uint32_t phys = (uint32_t)(c ^ (r & 7));
        CP_ASYNC16(sb + 16384 + r * 128 + phys * 16, B + (size_t)(n0 + r) * K + k0 + c * 4);
    }
}

template<int ACT, bool RES>
__global__ __launch_bounds__(256, 2) void gemm_tf32(
    const float* __restrict__ A, const float* __restrict__ Bt,
    const float* __restrict__ bias, const float* __restrict__ bias2,
    const float* __restrict__ bias3, const float* __restrict__ res,
    float* __restrict__ Cf, float* __restrict__ Cf2, float* __restrict__ Cf3,
    int M, int N, int K)
{
    extern __shared__ char smem[];
    uint32_t sbase = smem_to_u32(smem);
    int tid = threadIdx.x;
    int wid = tid >> 5, l = tid & 31;
    int warpM = wid >> 2, warpN = wid & 3;     // 2 x 4 warps, warp tile 64x32
    int m0 = blockIdx.y * 128, n0 = blockIdx.x * 128;

    // lane addressing for ldmatrix (b16-view of tf32 tiles; 128B rows, 8 chunks)
    int xr = l & 7;                                   // swizzle xor
    int rowlaneA = (l & 7) + ((l >> 3) & 1) * 8;      // 0..15 within m16
    int chA = (l >> 4) & 1;
    int rowlaneB = ((l >> 4) & 1) * 8 + (l & 7);
    int chB = (l >> 3) & 1;

    float acc[4][4][4];
#pragma unroll
    for (int mi = 0; mi < 4; mi++)
#pragma unroll
        for (int ni = 0; ni < 4; ni++)
#pragma unroll
            for (int j = 0; j < 4; j++) acc[mi][ni][j] = 0.0f;

    const int NC = K >> 5;                 // K-chunk 32
    load_stage(sbase, 0, tid, m0, n0, 0, K, A, Bt);
    CP_COMMIT();
    load_stage(sbase, 1, tid, m0, n0, 32, K, A, Bt);
    CP_COMMIT();

    int slot = 0, nslot = 2;
    for (int c = 0; c < NC; c++) {
        CP_WAIT1();
        __syncthreads();     // data for chunk c visible; all warps done with chunk c-1
        if (c + 2 < NC)
            load_stage(sbase, nslot, tid, m0, n0, (c + 2) * 32, K, A, Bt);
        CP_COMMIT();
        uint32_t sA = sbase + slot * STAGE_BYTES;
        uint32_t sB = sA + 16384;
#pragma unroll
        for (int k8 = 0; k8 < 4; k8++) {
            uint32_t Af[4][4], Bf[4][2];
            {
                int cl = 2 * k8 + chA;
                uint32_t phys = (uint32_t)(cl ^ xr);
#pragma unroll
                for (int mi = 0; mi < 4; mi++) {
                    uint32_t ad = sA + (uint32_t)((warpM * 64 + mi * 16 + rowlaneA) * 128) + phys * 16;
                    LDSM_X4(Af[mi][0], Af[mi][1], Af[mi][2], Af[mi][3], ad);
                }
            }
            {
                int cl = 2 * k8 + chB;
                uint32_t phys = (uint32_t)(cl ^ xr);
#pragma unroll
                for (int np = 0; np < 2; np++) {
                    uint32_t bd = sB + (uint32_t)((warpN * 32 + np * 16 + rowlaneB) * 128) + phys * 16;
                    uint32_t t0, t1, t2, t3;
                    LDSM_X4(t0, t1, t2, t3, bd);
                    Bf[np*2][0] = t0; Bf[np*2][1] = t1;
                    Bf[np*2+1][0] = t2; Bf[np*2+1][1] = t3;
                }
            }
#pragma unroll
            for (int mi = 0; mi < 4; mi++)
#pragma unroll
                for (int ni = 0; ni < 4; ni++)
                    MMA_TF32(acc[mi][ni], Af[mi], Bf[ni]);
        }
        slot = slot == 2 ? 0 : slot + 1;
        nslot = nslot == 2 ? 0 : nslot + 1;
    }

    // ---------------- epilogue ----------------
    int sec = n0 >> 10;                       // uniform per CTA (ACT3)
    const float* bsel = (ACT == 3) ? (sec == 0 ? bias : (sec == 1 ? bias2 : bias3)) : bias;
    float* dst = (ACT == 3) ? (sec == 0 ? Cf : (sec == 1 ? Cf2 : Cf3)) : Cf;
    int nsub = (ACT == 3) ? (sec << 10) : 0;
    int rowstride = (ACT == 3) ? Ee : N;
#pragma unroll
    for (int mi = 0; mi < 4; mi++) {
#pragma unroll
        for (int half = 0; half < 2; half++) {
            int m = m0 + warpM * 64 + mi * 16 + (l >> 2) + half * 8;
#pragma unroll
            for (int ni = 0; ni < 4; ni++) {
                int n = n0 + warpN * 32 + ni * 8 + (l & 3) * 2;
                float v0 = acc[mi][ni][half * 2 + 0];
                float v1 = acc[mi][ni][half * 2 + 1];
                float2 bz = __ldg((const float2*)&bsel[n - nsub]);
                v0 += bz.x; v1 += bz.y;
                if (ACT == 1 || (ACT == 3 && sec < 2)) {
                    v0 = fmaxf(v0, 0.0f); v1 = fmaxf(v1, 0.0f);
                } else if (ACT == 2) {
                    v0 = 0.5f * v0 * (1.0f + erff(v0 * 0.70710678118654752f));
                    v1 = 0.5f * v1 * (1.0f + erff(v1 * 0.70710678118654752f));
                    v0 = to_tf32(v0); v1 = to_tf32(v1);   // feeds next GEMM A-operand
                }
                size_t off = (size_t)m * rowstride + (n - nsub);
                if (RES) {
                    float2 rv = *(const float2*)&res[off];
                    v0 += rv.x; v1 += rv.y;
                }
                *(float2*)&dst[off] = make_float2(v0, v1);
            }
        }
    }
}

// ===================== zero (kv + ksum in one launch) =====================
__global__ void zero2_kernel(float* p1, int n1, float* p2, int n2) {
    int i = blockIdx.x * blockDim.x + threadIdx.x;
    if (i < n1) p1[i] = 0.0f;
    if (i < n2) p2[i] = 0.0f;
}

// ===================== kv reduction =====================
#define TSPLIT 8
__global__ __launch_bounds__(256) void kv_kernel(
    const float* __restrict__ Kp, const float* __restrict__ Vp,
    float* __restrict__ kv, float* __restrict__ ksum)
{
    int bh = blockIdx.x;
    int b = bh >> 4, h = bh & 15;
    int tid = threadIdx.x;
    __shared__ float ks_sh[32][64];
    __shared__ float vs_sh[32][64];
    __shared__ float s_sh[32], c_sh[32];

    int dd = tid & 63;
    int eb = tid >> 6;
    int e0 = eb * 16;
    float acc_s[16], acc_c[16];
#pragma unroll
    for (int i = 0; i < 16; i++) { acc_s[i] = 0.0f; acc_c[i] = 0.0f; }
    float ksum_s = 0.0f, ksum_c = 0.0f;

    int tbase = blockIdx.y * (Tt / TSPLIT);
    for (int tt = 0; tt < Tt / TSPLIT; tt += 32) {
        int t0 = tbase + tt;
#pragma unroll
        for (int ld = 0; ld < 2; ld++) {
            int id = tid + ld * 256;
            int r = id >> 4, c4 = (id & 15) * 4;
            size_t off = (size_t)(b * Tt + t0 + r) * Ee + h * 64 + c4;
            *(float4*)&ks_sh[r][c4] = *(const float4*)&Kp[off];
            *(float4*)&vs_sh[r][c4] = *(const float4*)&Vp[off];
        }
        if (tid < 32) {
            float idx = PIO2 * (float)(t0 + tid + 1) * (1.0f / Tt);
            s_sh[tid] = sinf(idx);
            c_sh[tid] = cosf(idx);
        }
        __syncthreads();
#pragma unroll 4
        for (int r = 0; r < 32; r++) {
            float kd = ks_sh[r][dd];
            float as = kd * s_sh[r];
            float ac = kd * c_sh[r];
            if (eb == 0) { ksum_s += as; ksum_c += ac; }
#pragma unroll
            for (int i = 0; i < 16; i++) {
                float ve = vs_sh[r][e0 + i];
                acc_s[i] = fmaf(as, ve, acc_s[i]);
                acc_c[i] = fmaf(ac, ve, acc_c[i]);
            }
        }
        __syncthreads();
    }
    float* kvb = kv + (size_t)bh * 128 * Dd;
#pragma unroll
    for (int i = 0; i < 16; i++) {
        atomicAdd(&kvb[dd * Dd + e0 + i], acc_s[i]);
        atomicAdd(&kvb[(64 + dd) * Dd + e0 + i], acc_c[i]);
    }
    if (eb == 0) {
        atomicAdd(&ksum[bh * 128 + dd], ksum_s);
        atomicAdd(&ksum[bh * 128 + 64 + dd], ksum_c);
    }
}

// ===================== attention: out -> tf32-rounded fp32 =================
__global__ __launch_bounds__(256) void attn_kernel(
    const float* __restrict__ Qp, const float* __restrict__ kv,
    const float* __restrict__ ksum, float* __restrict__ Op)
{
    int bh = blockIdx.y;
    int b = bh >> 4, h = bh & 15;
    int t0 = blockIdx.x * 32;
    int tid = threadIdx.x;

    __shared__ float kv_sh[128][64];
    __shared__ float q_sh[32][65];
    __shared__ float ksum_sh[128];
    __shared__ float den_sh[32], s_sh[32], c_sh[32];

#pragma unroll
    for (int ld = 0; ld < 8; ld++) {
        int id = tid + ld * 256;
        int r = id >> 4, c4 = (id & 15) * 4;
        *(float4*)&kv_sh[r][c4] = *(const float4*)&kv[((size_t)bh * 128 + r) * Dd + c4];
    }
#pragma unroll
    for (int ld = 0; ld < 2; ld++) {
        int id = tid + ld * 256;
        int r = id >> 4, c4 = (id & 15) * 4;
        float4 qv = *(const float4*)&Qp[(size_t)(b * Tt + t0 + r) * Ee + h * 64 + c4];
        q_sh[r][c4 + 0] = qv.x; q_sh[r][c4 + 1] = qv.y;
        q_sh[r][c4 + 2] = qv.z; q_sh[r][c4 + 3] = qv.w;
    }
    if (tid < 128) ksum_sh[tid] = ksum[bh * 128 + tid];
    if (tid < 32) {
        float idx = PIO2 * (float)(t0 + tid + 1) * (1.0f / Tt);
        s_sh[tid] = sinf(idx);
        c_sh[tid] = cosf(idx);
    }
    __syncthreads();

    if (tid < 32) {
        float ds = 0.0f, dc = 0.0f;
#pragma unroll 8
        for (int d = 0; d < 64; d++) {
            float qd = q_sh[tid][d];
            ds = fmaf(qd, ksum_sh[d], ds);
            dc = fmaf(qd, ksum_sh[64 + d], dc);
        }
        den_sh[tid] = s_sh[tid] * ds + c_sh[tid] * dc;
    }
    __syncthreads();

    int tl = tid & 31;
    int eb = tid >> 5;
    int e0 = eb * 8;
    float outs[8], outc[8];
#pragma unroll
    for (int j = 0; j < 8; j++) { outs[j] = 0.0f; outc[j] = 0.0f; }

#pragma unroll 4
    for (int d = 0; d < 64; d++) {
        float qd = q_sh[tl][d];
        float4 k0 = *(const float4*)&kv_sh[d][e0];
        float4 k1 = *(const float4*)&kv_sh[d][e0 + 4];
        float4 m0 = *(const float4*)&kv_sh[64 + d][e0];
        float4 m1 = *(const float4*)&kv_sh[64 + d][e0 + 4];
        outs[0]=fmaf(qd,k0.x,outs[0]); outs[1]=fmaf(qd,k0.y,outs[1]);
        outs[2]=fmaf(qd,k0.z,outs[2]); outs[3]=fmaf(qd,k0.w,outs[3]);
        outs[4]=fmaf(qd,k1.x,outs[4]); outs[5]=fmaf(qd,k1.y,outs[5]);
        outs[6]=fmaf(qd,k1.z,outs[6]); outs[7]=fmaf(qd,k1.w,outs[7]);
        outc[0]=fmaf(qd,m0.x,outc[0]); outc[1]=fmaf(qd,m0.y,outc[1]);
        outc[2]=fmaf(qd,m0.z,outc[2]); outc[3]=fmaf(qd,m0.w,outc[3]);
        outc[4]=fmaf(qd,m1.x,outc[4]); outc[5]=fmaf(qd,m1.y,outc[5]);
        outc[6]=fmaf(qd,m1.z,outc[6]); outc[7]=fmaf(qd,m1.w,outc[7]);
    }
    float z = 1.0f / fmaxf(den_sh[tl], 1e-6f);
    float s = s_sh[tl] * z, c = c_sh[tl] * z;
    float o[8];
#pragma unroll
    for (int j = 0; j < 8; j++) o[j] = to_tf32(s * outs[j] + c * outc[j]);
    size_t off = (size_t)(b * Tt + t0 + tl) * Ee + h * 64 + e0;
    *(float4*)&Op[off]     = make_float4(o[0], o[1], o[2], o[3]);
    *(float4*)&Op[off + 4] = make_float4(o[4], o[5], o[6], o[7]);
}

// ===================== launch =====================
extern "C" void kernel_launch(void* const* d_in, const int* in_sizes, int n_in,
                              void* d_out, int out_size) {
    const float* x      = (const float*)d_in[0];
    const float* ln1_w  = (const float*)d_in[1];
    const float* ln1_b  = (const float*)d_in[2];
    const float* wq     = (const float*)d_in[3];
    const float* bq     = (const float*)d_in[4];
    const float* wk     = (const float*)d_in[5];
    const float* bk     = (const float*)d_in[6];
    const float* wv     = (const float*)d_in[7];
    const float* bv     = (const float*)d_in[8];
    const float* wo     = (const float*)d_in[9];
    const float* bo     = (const float*)d_in[10];
    const float* ln2_w  = (const float*)d_in[11];
    const float* ln2_b  = (const float*)d_in[12];
    const float* w_fc   = (const float*)d_in[13];
    const float* b_fc   = (const float*)d_in[14];
    const float* w_proj = (const float*)d_in[15];
    const float* b_proj = (const float*)d_in[16];
    float* out = (float*)d_out;

    float *p_h, *p_attn, *p_fc, *p_q, *p_k, *p_v, *p_x2, *p_kv, *p_ksum;
    float *p_wqkv, *p_wo, *p_wfc, *p_wpj;
    cudaGetSymbolAddress((void**)&p_h,    g_h);
    cudaGetSymbolAddress((void**)&p_attn, g_attn);
    cudaGetSymbolAddress((void**)&p_fc,   g_fc);
    cudaGetSymbolAddress((void**)&p_q,    g_q);
    cudaGetSymbolAddress((void**)&p_k,    g_k);
    cudaGetSymbolAddress((void**)&p_v,    g_v);
    cudaGetSymbolAddress((void**)&p_x2,   g_x2);
    cudaGetSymbolAddress((void**)&p_kv,   g_kv);
    cudaGetSymbolAddress((void**)&p_ksum, g_ksum);
    cudaGetSymbolAddress((void**)&p_wqkv, g_wqkv);
    cudaGetSymbolAddress((void**)&p_wo,   g_wo);
    cudaGetSymbolAddress((void**)&p_wfc,  g_wfc);
    cudaGetSymbolAddress((void**)&p_wpj,  g_wpj);

    cudaFuncSetAttribute(gemm_tf32<3, false>, cudaFuncAttributeMaxDynamicSharedMemorySize, GT_SMEM);
    cudaFuncSetAttribute(gemm_tf32<0, true>,  cudaFuncAttributeMaxDynamicSharedMemorySize, GT_SMEM);
    cudaFuncSetAttribute(gemm_tf32<2, false>, cudaFuncAttributeMaxDynamicSharedMemorySize, GT_SMEM);

    // launch 0: h = LN1(x)
    ln_kernel<<<M_ROWS, 256>>>(x, ln1_w, ln1_b, p_h);
    // launch 1: QKV weight transpose (all 3 in one launch)
    transpose_qkv_kernel<<<dim3(Ee/32, Ee/32, 3), 256>>>(wq, wk, wv, p_wqkv);
    // launch 2: wo transpose
    transpose_tf32_kernel<<<dim3(Ee/32, Ee/32), 256>>>(wo, p_wo, Ee, Ee);
    // launch 3 (ncu capture target): fused QKV GEMM, N=3072
    dim3 gqkv(3*Ee / 128, M_ROWS / 128);
    gemm_tf32<3, false><<<gqkv, 256, GT_SMEM>>>(p_h, p_wqkv,
        bq, bk, bv, nullptr, p_q, p_k, p_v, M_ROWS, 3*Ee, Ee);

    // kv / ksum reduction
    zero2_kernel<<<(Bb*Hh*128*Dd + 255) / 256, 256>>>(p_kv, Bb*Hh*128*Dd, p_ksum, Bb*Hh*128);
    kv_kernel<<<dim3(Bb * Hh, TSPLIT), 256>>>(p_k, p_v, p_kv, p_ksum);

    // attention output (tf32-rounded fp32)
    attn_kernel<<<dim3(Tt / 32, Bb * Hh), 256>>>(p_q, p_kv, p_ksum, p_attn);

    // x2 = x + attn @ wo + bo
    dim3 g1(Ee / 128, M_ROWS / 128);
    gemm_tf32<0, true><<<g1, 256, GT_SMEM>>>(p_attn, p_wo,
        bo, nullptr, nullptr, x, p_x2, nullptr, nullptr, M_ROWS, Ee, Ee);

    // h = LN2(x2)
    ln_kernel<<<M_ROWS, 256>>>(p_x2, ln2_w, ln2_b, p_h);

    // fc = gelu(h @ w_fc + b_fc)  (tf32-rounded)
    transpose_tf32_kernel<<<dim3(FF/32, Ee/32), 256>>>(w_fc, p_wfc, Ee, FF);
    dim3 g2(FF / 128, M_ROWS / 128);
    gemm_tf32<2, false><<<g2, 256, GT_SMEM>>>(p_h, p_wfc,
        b_fc, nullptr, nullptr, nullptr, p_fc, nullptr, nullptr, M_ROWS, FF, Ee);

    // out = x2 + fc @ w_proj + b_proj
    transpose_tf32_kernel<<<dim3(Ee/32, FF/32), 256>>>(w_proj, p_wpj, FF, Ee);
    gemm_tf32<0, true><<<g1, 256, GT_SMEM>>>(p_fc, p_wpj,
        b_proj, nullptr, nullptr, p_x2, out, nullptr, nullptr, M_ROWS, Ee, FF);
}

// round 10
// speedup vs baseline: 7.0074x; 1.6273x over previous
#include <cuda_runtime.h>
#include <cuda_fp16.h>
#include <math.h>
#include <stdint.h>

#define Bb 4
#define Tt 4096
#define Ee 1024
#define Hh 16
#define Dd 64
#define M_ROWS (Bb*Tt)          // 16384
#define FF (4*Ee)               // 4096
#define PIO2 1.5707963267948966f

// ===================== PTX helpers (baseline ISA only) =====================
__device__ __forceinline__ uint32_t smem_to_u32(const void* p) {
    uint32_t a;
    asm("{ .reg .u64 t; cvta.to.shared.u64 t, %1; cvt.u32.u64 %0, t; }" : "=r"(a) : "l"(p));
    return a;
}
#define CP_ASYNC16(saddr, gptr) \
    asm volatile("cp.async.cg.shared.global [%0], [%1], 16;" :: "r"(saddr), "l"(gptr))
#define CP_COMMIT() asm volatile("cp.async.commit_group;" ::: "memory")
#define CP_WAIT1()  asm volatile("cp.async.wait_group 1;" ::: "memory")

#define LDSM_X4(r0,r1,r2,r3, addr) \
    asm volatile("ldmatrix.sync.aligned.m8n8.x4.shared.b16 {%0,%1,%2,%3}, [%4];" \
        : "=r"(r0),"=r"(r1),"=r"(r2),"=r"(r3) : "r"(addr))

#define MMA_F16(d, a, b) \
    asm volatile("mma.sync.aligned.m16n8k16.row.col.f32.f16.f16.f32 " \
        "{%0,%1,%2,%3}, {%4,%5,%6,%7}, {%8,%9}, {%0,%1,%2,%3};" \
        : "+f"((d)[0]),"+f"((d)[1]),"+f"((d)[2]),"+f"((d)[3]) \
        : "r"((a)[0]),"r"((a)[1]),"r"((a)[2]),"r"((a)[3]), "r"((b)[0]),"r"((b)[1]))

__device__ __forceinline__ uint32_t pack_h2(float a, float b) {
    __half2 h = __floats2half2_rn(a, b);
    return *(uint32_t*)&h;
}

// ===================== scratch (device globals) =====================
__device__ __half g_h   [M_ROWS*Ee];           // LN out (fp16)
__device__ __half g_attn[M_ROWS*Ee];           // attn out (fp16)
__device__ __half g_fc  [(size_t)M_ROWS*FF];   // gelu out (fp16)
__device__ float g_q [M_ROWS*Ee];
__device__ float g_k [M_ROWS*Ee];
__device__ float g_v [M_ROWS*Ee];
__device__ float g_x2[M_ROWS*Ee];
__device__ float g_kv  [Bb*Hh*128*Dd];
__device__ float g_ksum[Bb*Hh*128];
// transposed fp16 weights: [N, K]
__device__ __half g_wqkv[3*Ee*Ee];             // q|k|v stacked in N
__device__ __half g_wo  [Ee*Ee];
__device__ __half g_wfc [(size_t)FF*Ee];
__device__ __half g_wpj [(size_t)Ee*FF];

// ===================== transpose + fp16: W[K,N] -> T[N,K] ============
__global__ void transpose_h_kernel(const float* __restrict__ W,
                                   __half* __restrict__ T, int K, int N) {
    __shared__ float ts[32][33];
    int n0 = blockIdx.x * 32, k0 = blockIdx.y * 32;
    int tx = threadIdx.x & 31, ty = threadIdx.x >> 5;
#pragma unroll
    for (int i = 0; i < 32; i += 8)
        ts[ty + i][tx] = W[(size_t)(k0 + ty + i) * N + n0 + tx];
    __syncthreads();
#pragma unroll
    for (int i = 0; i < 32; i += 8)
        T[(size_t)(n0 + ty + i) * K + k0 + tx] = __float2half_rn(ts[tx][ty + i]);
}

// all three QKV weights in one launch (blockIdx.z selects)
__global__ void transpose_qkv_kernel(const float* __restrict__ wq,
                                     const float* __restrict__ wk,
                                     const float* __restrict__ wv,
                                     __half* __restrict__ T) {
    __shared__ float ts[32][33];
    const float* W = blockIdx.z == 0 ? wq : (blockIdx.z == 1 ? wk : wv);
    __half* Tz = T + (size_t)blockIdx.z * Ee * Ee;
    int n0 = blockIdx.x * 32, k0 = blockIdx.y * 32;
    int tx = threadIdx.x & 31, ty = threadIdx.x >> 5;
#pragma unroll
    for (int i = 0; i < 32; i += 8)
        ts[ty + i][tx] = W[(size_t)(k0 + ty + i) * Ee + n0 + tx];
    __syncthreads();
#pragma unroll
    for (int i = 0; i < 32; i += 8)
        Tz[(size_t)(n0 + ty + i) * Ee + k0 + tx] = __float2half_rn(ts[tx][ty + i]);
}

// ===================== LayerNorm -> fp16 =====================
__global__ void ln_kernel(const float* __restrict__ X, const float* __restrict__ w,
                          const float* __restrict__ b, __half* __restrict__ Y) {
    int row = blockIdx.x;
    int tid = threadIdx.x;                 // 256 threads
    const float4* x4 = (const float4*)(X + (size_t)row * Ee);
    float4 v = x4[tid];
    __shared__ float red[8];

    float s = v.x + v.y + v.z + v.w;
    for (int o = 16; o > 0; o >>= 1) s += __shfl_down_sync(0xffffffffu, s, o);
    if ((tid & 31) == 0) red[tid >> 5] = s;
    __syncthreads();
    if (tid < 8) {
        float t = red[tid];
        for (int o = 4; o > 0; o >>= 1) t += __shfl_down_sync(0xffu, t, o);
        if (tid == 0) red[0] = t;
    }
    __syncthreads();
    float mu = red[0] * (1.0f / Ee);
    __syncthreads();

    float dx = v.x - mu, dy = v.y - mu, dz = v.z - mu, dw = v.w - mu;
    float ss = dx*dx + dy*dy + dz*dz + dw*dw;
    for (int o = 16; o > 0; o >>= 1) ss += __shfl_down_sync(0xffffffffu, ss, o);
    if ((tid & 31) == 0) red[tid >> 5] = ss;
    __syncthreads();
    if (tid < 8) {
        float t = red[tid];
        for (int o = 4; o > 0; o >>= 1) t += __shfl_down_sync(0xffu, t, o);
        if (tid == 0) red[0] = t;
    }
    __syncthreads();
    float rstd = rsqrtf(red[0] * (1.0f / Ee) + 1e-5f);

    float4 wv = ((const float4*)w)[tid];
    float4 bv = ((const float4*)b)[tid];
    uint32_t h0 = pack_h2(dx * rstd * wv.x + bv.x, dy * rstd * wv.y + bv.y);
    uint32_t h1 = pack_h2(dz * rstd * wv.z + bv.z, dw * rstd * wv.w + bv.w);
    *(uint2*)&Y[(size_t)row * Ee + tid * 4] = make_uint2(h0, h1);
}

// ===================== fp16 mma.sync GEMM ==================================
// C[m,n] = act( A[m,:] @ Bt[n,:]^T + bias[n] ) (+ res)
// A: [M,K] fp16, Bt: [N,K] fp16. Tile 128x128, K-chunk 64 (128B rows),
// 3-stage cp.async pipeline, 8 warps (warp 64x32), 2 CTAs/SM.
// ACT: 0 none (fp32 out), 2 gelu (fp16 out), 3 fused-QKV (fp32 out x3, relu sec<2).
#define STAGE_BYTES 32768        // A 16KB + B 16KB (K-chunk 64 x fp16)
#define GT_SMEM (3*STAGE_BYTES)  // 96KB -> 2 CTAs/SM

__device__ __forceinline__ void load_stage(
    uint32_t sbase, int slot, int tid, int m0, int n0, int k0, int K,
    const __half* A, const __half* B)
{
    uint32_t sb = sbase + slot * STAGE_BYTES;
#pragma unroll
    for (int i = 0; i < 4; i++) {
        int u = tid + i * 256;        // 0..1023: 128 rows x 8 16B-chunks
        int r = u >> 3, c = u & 7;
        uint32_t soff = (uint32_t)(r * 128) + (uint32_t)(((c ^ (r & 7)) << 4));
        CP_ASYNC16(sb + soff, A + (size_t)(m0 + r) * K + k0 + c * 8);
    }
#pragma unroll
    for (int i = 0; i < 4; i++) {
        int u = tid + i * 256;
        int r = u >> 3, c = u & 7;
        uint32_t soff = (uint32_t)(r * 128) + (uint32_t)(((c ^ (r & 7)) << 4));
        CP_ASYNC16(sb + 16384 + soff, B + (size_t)(n0 + r) * K + k0 + c * 8);
    }
}

template<int ACT, bool RES>
__global__ __launch_bounds__(256, 2) void gemm_h(
    const __half* __restrict__ A, const __half* __restrict__ Bt,
    const float* __restrict__ bias, const float* __restrict__ bias2,
    const float* __restrict__ bias3, const float* __restrict__ res,
    float* __restrict__ Cf, float* __restrict__ Cf2, float* __restrict__ Cf3,
    __half* __restrict__ Ch,
    int M, int N, int K)
{
    extern __shared__ char smem[];
    uint32_t sbase = smem_to_u32(smem);
    int tid = threadIdx.x;
    int wid = tid >> 5, l = tid & 31;
    int warpM = wid >> 2, warpN = wid & 3;     // 2 x 4 warps, warp tile 64x32
    int m0 = blockIdx.y * 128, n0 = blockIdx.x * 128;

    // ldmatrix lane addressing (validated in R4 with bf16, identical for fp16)
    int g = l & 7, grp = l >> 3;
    uint32_t constA = (uint32_t)((warpM * 64 + (grp & 1) * 8 + g) * 128);
    int khA = grp >> 1;
    uint32_t constB = (uint32_t)((warpN * 32 + (grp >> 1) * 8 + g) * 128);
    int khB = grp & 1;

    float acc[4][4][4];
#pragma unroll
    for (int mi = 0; mi < 4; mi++)
#pragma unroll
        for (int ni = 0; ni < 4; ni++)
#pragma unroll
            for (int j = 0; j < 4; j++) acc[mi][ni][j] = 0.0f;

    const int NC = K >> 6;                 // K-chunk 64
    load_stage(sbase, 0, tid, m0, n0, 0, K, A, Bt);
    CP_COMMIT();
    load_stage(sbase, 1, tid, m0, n0, 64, K, A, Bt);
    CP_COMMIT();

    int slot = 0, nslot = 2;
    for (int c = 0; c < NC; c++) {
        CP_WAIT1();
        __syncthreads();     // chunk c visible; all warps done with old slot data
        if (c + 2 < NC)
            load_stage(sbase, nslot, tid, m0, n0, (c + 2) * 64, K, A, Bt);
        CP_COMMIT();
        uint32_t sA = sbase + slot * STAGE_BYTES;
        uint32_t sB = sA + 16384;
#pragma unroll
        for (int ks = 0; ks < 4; ks++) {
            uint32_t Af[4][4], Bf[4][2];
            uint32_t segA = (uint32_t)(((ks * 2 + khA) ^ g) << 4);
            uint32_t segB = (uint32_t)(((ks * 2 + khB) ^ g) << 4);
#pragma unroll
            for (int mi = 0; mi < 4; mi++) {
                uint32_t ad = sA + constA + mi * 2048 + segA;
                LDSM_X4(Af[mi][0], Af[mi][1], Af[mi][2], Af[mi][3], ad);
            }
#pragma unroll
            for (int np = 0; np < 2; np++) {
                uint32_t bd = sB + constB + np * 2048 + segB;
                uint32_t t0, t1, t2, t3;
                LDSM_X4(t0, t1, t2, t3, bd);
                Bf[np*2][0] = t0; Bf[np*2][1] = t1;
                Bf[np*2+1][0] = t2; Bf[np*2+1][1] = t3;
            }
#pragma unroll
            for (int mi = 0; mi < 4; mi++)
#pragma unroll
                for (int ni = 0; ni < 4; ni++)
                    MMA_F16(acc[mi][ni], Af[mi], Bf[ni]);
        }
        slot = slot == 2 ? 0 : slot + 1;
        nslot = nslot == 2 ? 0 : nslot + 1;
    }

    // ---------------- epilogue ----------------
    int sec = n0 >> 10;                       // uniform per CTA (ACT3)
    const float* bsel = (ACT == 3) ? (sec == 0 ? bias : (sec == 1 ? bias2 : bias3)) : bias;
    float* dst = (ACT == 3) ? (sec == 0 ? Cf : (sec == 1 ? Cf2 : Cf3)) : Cf;
    int nsub = (ACT == 3) ? (sec << 10) : 0;
    int rowstride = (ACT == 3) ? Ee : N;
#pragma unroll
    for (int mi = 0; mi < 4; mi++) {
#pragma unroll
        for (int half_ = 0; half_ < 2; half_++) {
            int m = m0 + warpM * 64 + mi * 16 + (l >> 2) + half_ * 8;
#pragma unroll
            for (int ni = 0; ni < 4; ni++) {
                int n = n0 + warpN * 32 + ni * 8 + (l & 3) * 2;
                float v0 = acc[mi][ni][half_ * 2 + 0];
                float v1 = acc[mi][ni][half_ * 2 + 1];
                float2 bz = __ldg((const float2*)&bsel[n - nsub]);
                v0 += bz.x; v1 += bz.y;
                if (ACT == 3 && sec < 2) {
                    v0 = fmaxf(v0, 0.0f); v1 = fmaxf(v1, 0.0f);
                } else if (ACT == 2) {
                    v0 = 0.5f * v0 * (1.0f + erff(v0 * 0.70710678118654752f));
                    v1 = 0.5f * v1 * (1.0f + erff(v1 * 0.70710678118654752f));
                }
                size_t off = (size_t)m * rowstride + (n - nsub);
                if (RES) {
                    float2 rv = *(const float2*)&res[off];
                    v0 += rv.x; v1 += rv.y;
                }
                if (ACT == 2) {
                    *(uint32_t*)&Ch[off] = pack_h2(v0, v1);
                } else {
                    *(float2*)&dst[off] = make_float2(v0, v1);
                }
            }
        }
    }
}

// ===================== zero (kv + ksum in one launch) =====================
__global__ void zero2_kernel(float* p1, int n1, float* p2, int n2) {
    int i = blockIdx.x * blockDim.x + threadIdx.x;
    if (i < n1) p1[i] = 0.0f;
    if (i < n2) p2[i] = 0.0f;
}

// ===================== kv reduction =====================
#define TSPLIT 8
__global__ __launch_bounds__(256) void kv_kernel(
    const float* __restrict__ Kp, const float* __restrict__ Vp,
    float* __restrict__ kv, float* __restrict__ ksum)
{
    int bh = blockIdx.x;
    int b = bh >> 4, h = bh & 15;
    int tid = threadIdx.x;
    __shared__ float ks_sh[32][64];
    __shared__ float vs_sh[32][64];
    __shared__ float s_sh[32], c_sh[32];

    int dd = tid & 63;
    int eb = tid >> 6;
    int e0 = eb * 16;
    float acc_s[16], acc_c[16];
#pragma unroll
    for (int i = 0; i < 16; i++) { acc_s[i] = 0.0f; acc_c[i] = 0.0f; }
    float ksum_s = 0.0f, ksum_c = 0.0f;

    int tbase = blockIdx.y * (Tt / TSPLIT);
    for (int tt = 0; tt < Tt / TSPLIT; tt += 32) {
        int t0 = tbase + tt;
#pragma unroll
        for (int ld = 0; ld < 2; ld++) {
            int id = tid + ld * 256;
            int r = id >> 4, c4 = (id & 15) * 4;
            size_t off = (size_t)(b * Tt + t0 + r) * Ee + h * 64 + c4;
            *(float4*)&ks_sh[r][c4] = *(const float4*)&Kp[off];
            *(float4*)&vs_sh[r][c4] = *(const float4*)&Vp[off];
        }
        if (tid < 32) {
            float idx = PIO2 * (float)(t0 + tid + 1) * (1.0f / Tt);
            s_sh[tid] = sinf(idx);
            c_sh[tid] = cosf(idx);
        }
        __syncthreads();
#pragma unroll 4
        for (int r = 0; r < 32; r++) {
            float kd = ks_sh[r][dd];
            float as = kd * s_sh[r];
            float ac = kd * c_sh[r];
            if (eb == 0) { ksum_s += as; ksum_c += ac; }
#pragma unroll
            for (int i = 0; i < 16; i++) {
                float ve = vs_sh[r][e0 + i];
                acc_s[i] = fmaf(as, ve, acc_s[i]);
                acc_c[i] = fmaf(ac, ve, acc_c[i]);
            }
        }
        __syncthreads();
    }
    float* kvb = kv + (size_t)bh * 128 * Dd;
#pragma unroll
    for (int i = 0; i < 16; i++) {
        atomicAdd(&kvb[dd * Dd + e0 + i], acc_s[i]);
        atomicAdd(&kvb[(64 + dd) * Dd + e0 + i], acc_c[i]);
    }
    if (eb == 0) {
        atomicAdd(&ksum[bh * 128 + dd], ksum_s);
        atomicAdd(&ksum[bh * 128 + 64 + dd], ksum_c);
    }
}

// ===================== attention: out -> fp16 =================
__global__ __launch_bounds__(256) void attn_kernel(
    const float* __restrict__ Qp, const float* __restrict__ kv,
    const float* __restrict__ ksum, __half* __restrict__ Op)
{
    int bh = blockIdx.y;
    int b = bh >> 4, h = bh & 15;
    int t0 = blockIdx.x * 32;
    int tid = threadIdx.x;

    __shared__ float kv_sh[128][64];
    __shared__ float q_sh[32][65];
    __shared__ float ksum_sh[128];
    __shared__ float den_sh[32], s_sh[32], c_sh[32];

#pragma unroll
    for (int ld = 0; ld < 8; ld++) {
        int id = tid + ld * 256;
        int r = id >> 4, c4 = (id & 15) * 4;
        *(float4*)&kv_sh[r][c4] = *(const float4*)&kv[((size_t)bh * 128 + r) * Dd + c4];
    }
#pragma unroll
    for (int ld = 0; ld < 2; ld++) {
        int id = tid + ld * 256;
        int r = id >> 4, c4 = (id & 15) * 4;
        float4 qv = *(const float4*)&Qp[(size_t)(b * Tt + t0 + r) * Ee + h * 64 + c4];
        q_sh[r][c4 + 0] = qv.x; q_sh[r][c4 + 1] = qv.y;
        q_sh[r][c4 + 2] = qv.z; q_sh[r][c4 + 3] = qv.w;
    }
    if (tid < 128) ksum_sh[tid] = ksum[bh * 128 + tid];
    if (tid < 32) {
        float idx = PIO2 * (float)(t0 + tid + 1) * (1.0f / Tt);
        s_sh[tid] = sinf(idx);
        c_sh[tid] = cosf(idx);
    }
    __syncthreads();

    if (tid < 32) {
        float ds = 0.0f, dc = 0.0f;
#pragma unroll 8
        for (int d = 0; d < 64; d++) {
            float qd = q_sh[tid][d];
            ds = fmaf(qd, ksum_sh[d], ds);
            dc = fmaf(qd, ksum_sh[64 + d], dc);
        }
        den_sh[tid] = s_sh[tid] * ds + c_sh[tid] * dc;
    }
    __syncthreads();

    int tl = tid & 31;
    int eb = tid >> 5;
    int e0 = eb * 8;
    float outs[8], outc[8];
#pragma unroll
    for (int j = 0; j < 8; j++) { outs[j] = 0.0f; outc[j] = 0.0f; }

#pragma unroll 4
    for (int d = 0; d < 64; d++) {
        float qd = q_sh[tl][d];
        float4 k0 = *(const float4*)&kv_sh[d][e0];
        float4 k1 = *(const float4*)&kv_sh[d][e0 + 4];
        float4 m0 = *(const float4*)&kv_sh[64 + d][e0];
        float4 m1 = *(const float4*)&kv_sh[64 + d][e0 + 4];
        outs[0]=fmaf(qd,k0.x,outs[0]); outs[1]=fmaf(qd,k0.y,outs[1]);
        outs[2]=fmaf(qd,k0.z,outs[2]); outs[3]=fmaf(qd,k0.w,outs[3]);
        outs[4]=fmaf(qd,k1.x,outs[4]); outs[5]=fmaf(qd,k1.y,outs[5]);
        outs[6]=fmaf(qd,k1.z,outs[6]); outs[7]=fmaf(qd,k1.w,outs[7]);
        outc[0]=fmaf(qd,m0.x,outc[0]); outc[1]=fmaf(qd,m0.y,outc[1]);
        outc[2]=fmaf(qd,m0.z,outc[2]); outc[3]=fmaf(qd,m0.w,outc[3]);
        outc[4]=fmaf(qd,m1.x,outc[4]); outc[5]=fmaf(qd,m1.y,outc[5]);
        outc[6]=fmaf(qd,m1.z,outc[6]); outc[7]=fmaf(qd,m1.w,outc[7]);
    }
    float z = 1.0f / fmaxf(den_sh[tl], 1e-6f);
    float s = s_sh[tl] * z, c = c_sh[tl] * z;
    uint32_t hp[4];
#pragma unroll
    for (int j = 0; j < 8; j += 2)
        hp[j >> 1] = pack_h2(s * outs[j] + c * outc[j], s * outs[j+1] + c * outc[j+1]);
    size_t off = (size_t)(b * Tt + t0 + tl) * Ee + h * 64 + e0;
    *(uint4*)&Op[off] = make_uint4(hp[0], hp[1], hp[2], hp[3]);
}

// ===================== launch =====================
extern "C" void kernel_launch(void* const* d_in, const int* in_sizes, int n_in,
                              void* d_out, int out_size) {
    const float* x      = (const float*)d_in[0];
    const float* ln1_w  = (const float*)d_in[1];
    const float* ln1_b  = (const float*)d_in[2];
    const float* wq     = (const float*)d_in[3];
    const float* bq     = (const float*)d_in[4];
    const float* wk     = (const float*)d_in[5];
    const float* bk     = (const float*)d_in[6];
    const float* wv     = (const float*)d_in[7];
    const float* bv     = (const float*)d_in[8];
    const float* wo     = (const float*)d_in[9];
    const float* bo     = (const float*)d_in[10];
    const float* ln2_w  = (const float*)d_in[11];
    const float* ln2_b  = (const float*)d_in[12];
    const float* w_fc   = (const float*)d_in[13];
    const float* b_fc   = (const float*)d_in[14];
    const float* w_proj = (const float*)d_in[15];
    const float* b_proj = (const float*)d_in[16];
    float* out = (float*)d_out;

    __half *p_h, *p_attn, *p_fc, *p_wqkv, *p_wo, *p_wfc, *p_wpj;
    float *p_q, *p_k, *p_v, *p_x2, *p_kv, *p_ksum;
    cudaGetSymbolAddress((void**)&p_h,    g_h);
    cudaGetSymbolAddress((void**)&p_attn, g_attn);
    cudaGetSymbolAddress((void**)&p_fc,   g_fc);
    cudaGetSymbolAddress((void**)&p_q,    g_q);
    cudaGetSymbolAddress((void**)&p_k,    g_k);
    cudaGetSymbolAddress((void**)&p_v,    g_v);
    cudaGetSymbolAddress((void**)&p_x2,   g_x2);
    cudaGetSymbolAddress((void**)&p_kv,   g_kv);
    cudaGetSymbolAddress((void**)&p_ksum, g_ksum);
    cudaGetSymbolAddress((void**)&p_wqkv, g_wqkv);
    cudaGetSymbolAddress((void**)&p_wo,   g_wo);
    cudaGetSymbolAddress((void**)&p_wfc,  g_wfc);
    cudaGetSymbolAddress((void**)&p_wpj,  g_wpj);

    cudaFuncSetAttribute(gemm_h<3, false>, cudaFuncAttributeMaxDynamicSharedMemorySize, GT_SMEM);
    cudaFuncSetAttribute(gemm_h<0, true>,  cudaFuncAttributeMaxDynamicSharedMemorySize, GT_SMEM);
    cudaFuncSetAttribute(gemm_h<2, false>, cudaFuncAttributeMaxDynamicSharedMemorySize, GT_SMEM);

    // launch 0: h = LN1(x)
    ln_kernel<<<M_ROWS, 256>>>(x, ln1_w, ln1_b, p_h);
    // launch 1: QKV weight transpose (all 3 in one launch)
    transpose_qkv_kernel<<<dim3(Ee/32, Ee/32, 3), 256>>>(wq, wk, wv, p_wqkv);
    // launch 2: wo transpose
    transpose_h_kernel<<<dim3(Ee/32, Ee/32), 256>>>(wo, p_wo, Ee, Ee);
    // launch 3 (ncu capture target): fused QKV GEMM, N=3072
    dim3 gqkv(3*Ee / 128, M_ROWS / 128);
    gemm_h<3, false><<<gqkv, 256, GT_SMEM>>>(p_h, p_wqkv,
        bq, bk, bv, nullptr, p_q, p_k, p_v, nullptr, M_ROWS, 3*Ee, Ee);

    // kv / ksum reduction
    zero2_kernel<<<(Bb*Hh*128*Dd + 255) / 256, 256>>>(p_kv, Bb*Hh*128*Dd, p_ksum, Bb*Hh*128);
    kv_kernel<<<dim3(Bb * Hh, TSPLIT), 256>>>(p_k, p_v, p_kv, p_ksum);

    // attention output (fp16)
    attn_kernel<<<dim3(Tt / 32, Bb * Hh), 256>>>(p_q, p_kv, p_ksum, p_attn);

    // x2 = x + attn @ wo + bo
    dim3 g1(Ee / 128, M_ROWS / 128);
    gemm_h<0, true><<<g1, 256, GT_SMEM>>>(p_attn, p_wo,
        bo, nullptr, nullptr, x, p_x2, nullptr, nullptr, nullptr, M_ROWS, Ee, Ee);

    // h = LN2(x2)
    ln_kernel<<<M_ROWS, 256>>>(p_x2, ln2_w, ln2_b, p_h);

    // fc = gelu(h @ w_fc + b_fc)  (fp16 out)
    transpose_h_kernel<<<dim3(FF/32, Ee/32), 256>>>(w_fc, p_wfc, Ee, FF);
    dim3 g2(FF / 128, M_ROWS / 128);
    gemm_h<2, false><<<g2, 256, GT_SMEM>>>(p_h, p_wfc,
        b_fc, nullptr, nullptr, nullptr, nullptr, nullptr, nullptr, p_fc, M_ROWS, FF, Ee);

    // out = x2 + fc @ w_proj + b_proj
    transpose_h_kernel<<<dim3(Ee/32, FF/32), 256>>>(w_proj, p_wpj, FF, Ee);
    gemm_h<0, true><<<g1, 256, GT_SMEM>>>(p_fc, p_wpj,
        b_proj, nullptr, nullptr, p_x2, out, nullptr, nullptr, nullptr, M_ROWS, Ee, FF);
}